// round 11
// baseline (speedup 1.0000x reference)
#include <cuda_runtime.h>
#include <cuda_bf16.h>
#include <math.h>
#include <stdint.h>

#define V 7
#define NODE_D 48
#define OP_D 48
#define HID 96
#define GCN_D 128
#define N_LAYERS 5
#define MLP_H 200
#define NONE_OP 3

#define G 8              // graphs per CTA -> 56 real rows of a 64-row GEMM
#define NTHREADS 256     // 8 warps: 2 m-tiles x 4 n-tiles of 32x32
#define PST 68           // packed bf16-pair stride in smem (u32 words per row)
#define WST 64           // packed W stride in global (u32 words per row)
#define NROWS 64

// ---- shared memory word (u32) offsets ----
#define APH 0                        // A hi pairs: 64*68 = 4352
#define APL (APH + NROWS*PST)        // 4352
#define YPH (APL + NROWS*PST)        // 8704  : Y hi pairs
#define YPL (YPH + NROWS*PST)        // 13056 : Y lo pairs
#define GS  (YPL + NROWS*PST)        // 17408 : gates 5*6*128 = 3840
#define BS  (GS + N_LAYERS*6*GCN_D)  // 21248 : biases 5*128 = 640
#define RMK (BS + N_LAYERS*GCN_D)    // 21888 : row masks 64
#define RGI (RMK + 64)               // 21952
#define RRD (RGI + 64)               // 22016
#define ZS  (RRD + 64)               // 22080 : z fp32, 8*132
#define SMEM_WORDS (ZS + 8*132)      // 23136 words = 92544 B

// Precomputed, batch-independent tables
__device__ float g_s0[V*GCN_D];
__device__ float g_gate[N_LAYERS*6*GCN_D];
__device__ uint32_t g_WPh[(N_LAYERS-1)*GCN_D*WST];  // W hi fragments [li][n][kpair]
__device__ uint32_t g_WPl[(N_LAYERS-1)*GCN_D*WST];  // W lo

__device__ __forceinline__ void mma16816(float* d, const uint32_t* a, const uint32_t* b) {
    asm volatile("mma.sync.aligned.m16n8k16.row.col.f32.bf16.bf16.f32 "
        "{%0,%1,%2,%3}, {%4,%5,%6,%7}, {%8,%9}, {%0,%1,%2,%3};"
        : "+f"(d[0]), "+f"(d[1]), "+f"(d[2]), "+f"(d[3])
        : "r"(a[0]), "r"(a[1]), "r"(a[2]), "r"(a[3]), "r"(b[0]), "r"(b[1]));
}

__device__ __forceinline__ float2 up2(uint32_t w) {
    __nv_bfloat162 b = *(__nv_bfloat162*)&w;
    return make_float2(__bfloat162float(b.x), __bfloat162float(b.y));
}
__device__ __forceinline__ uint32_t dn2(float x, float y) {
    __nv_bfloat162 b = __floats2bfloat162_rn(x, y);
    return *(uint32_t*)&b;
}

__global__ void precompute_kernel(
    const float* __restrict__ input_node_emb,
    const float* __restrict__ other_node_emb,
    const float* __restrict__ input_op_emb,
    const float* __restrict__ op_emb_table,
    const float* __restrict__ output_op_emb,
    const float* __restrict__ xh_w,
    const float* __restrict__ xh_b,
    const float* __restrict__ gcn0_w,
    const float* __restrict__ attn_w,
    const float* __restrict__ attn_b)
{
    __shared__ float y0[2][HID];
    int t = threadIdx.x;
    if (t < 2*HID) {
        int r = t / HID, c = t % HID;
        const float* e = (r == 0) ? input_node_emb : other_node_emb;
        float acc = xh_b[c];
        for (int d = 0; d < NODE_D; d++) acc += e[d] * xh_w[d*HID + c];
        y0[r][c] = acc;
    }
    __syncthreads();
    for (int idx = t; idx < V*GCN_D; idx += blockDim.x) {
        int v = idx / GCN_D, n = idx % GCN_D;
        const float* yr = y0[(v == 0) ? 0 : 1];
        float acc = 0.f;
        for (int d = 0; d < HID; d++) acc += yr[d] * gcn0_w[d*GCN_D + n];
        g_s0[idx] = acc;
    }
    for (int idx = t; idx < N_LAYERS*6*GCN_D; idx += blockDim.x) {
        int i = idx / (6*GCN_D);
        int r = idx % (6*GCN_D);
        int gi = r / GCN_D, n = r % GCN_D;
        const float* e = (gi == 0) ? input_op_emb
                       : (gi <= 4 ? op_emb_table + (gi-1)*OP_D : output_op_emb);
        float acc = attn_b[i*GCN_D + n];
        for (int d = 0; d < OP_D; d++) acc += e[d] * attn_w[(i*OP_D + d)*GCN_D + n];
        g_gate[idx] = 1.f / (1.f + expf(-acc));
    }
}

// Pack W into mma B-fragment layout: [li][n][kpair], hi/lo split.
__global__ void prep_w_kernel(const float* __restrict__ gcn_w) {
    int idx = blockIdx.x * blockDim.x + threadIdx.x;
    if (idx >= (N_LAYERS-1)*GCN_D*WST) return;
    int li = idx >> 13;
    int r  = idx & 8191;
    int n  = r >> 6, kp = r & 63;
    const float* wl = gcn_w + (size_t)li*GCN_D*GCN_D;
    float w0 = wl[(2*kp)*GCN_D + n];
    float w1 = wl[(2*kp+1)*GCN_D + n];
    __nv_bfloat162 h = __floats2bfloat162_rn(w0, w1);
    __nv_bfloat162 l = __floats2bfloat162_rn(w0 - __bfloat162float(h.x),
                                             w1 - __bfloat162float(h.y));
    g_WPh[idx] = *(uint32_t*)&h;
    g_WPl[idx] = *(uint32_t*)&l;
}

__global__ __launch_bounds__(NTHREADS, 2) void nb101_main(
    const float* __restrict__ adjs,
    const int*   __restrict__ op_inds,
    const float* __restrict__ gcn_b,
    const float* __restrict__ mlp_w1,
    const float* __restrict__ mlp_b1,
    const float* __restrict__ mlp_w2,
    const float* __restrict__ mlp_b2,
    float* __restrict__ out,
    int Btot)
{
    extern __shared__ uint32_t smw[];
    float* smf = (float*)smw;
    int*   RMKp = (int*)(smw + RMK);
    int*   RGIp = (int*)(smw + RGI);
    float* RRDp = (float*)(smw + RRD);

    const int t  = threadIdx.x;
    const int tx = t & 31;
    const int ty = t >> 5;           // warp id 0..7
    const int gq = tx >> 2;          // mma group id (0..7)
    const int tq = tx & 3;           // thread-in-group
    const int mw = ty >> 2;          // warp m-tile (rows mw*32)
    const int nw = ty & 3;           // warp n-tile (cols nw*32)
    const int gbase = blockIdx.x * G;

    // stage gate/bias tables
    for (int i = t; i < N_LAYERS*6*GCN_D; i += NTHREADS) smf[GS + i] = g_gate[i];
    for (int i = t; i < N_LAYERS*GCN_D;   i += NTHREADS) smf[BS + i] = gcn_b[i];

    // per-row metadata (rows 0..55 real, 56..63 pad)
    if (t < NROWS) {
        int m = 0, gi = 0; float rw = 0.f;
        if (t < G*V) {
            int g = t / V, u = t - g*V;
            int batch = gbase + g;
            if (batch < Btot) {
                const float* arow = adjs + (size_t)batch*(V*V) + u*V;
                m = 1 << u;
                #pragma unroll
                for (int v2 = 0; v2 < V; v2++) if (arow[v2] != 0.f) m |= 1 << v2;
                if (u == 0)        { gi = 0; rw = 0.f; }
                else if (u == V-1) { gi = 5; rw = 1.f/6.f; }
                else {
                    int op = op_inds[(size_t)batch*(V-2) + (u-1)];
                    gi = 1 + op;
                    rw = (op != NONE_OP) ? (1.f/6.f) : 0.f;
                }
            }
        }
        RMKp[t] = m; RGIp[t] = gi; RRDp[t] = rw;
    }
    __syncthreads();

    // ----- layer 0: Y1 = relu(gate0 * (A_aug @ S0) + b0), stored packed hi/lo -----
    {
        const int g = ty, c0 = tx*4;
        float4 sv[V];
        #pragma unroll
        for (int v = 0; v < V; v++) sv[v] = __ldg((const float4*)(g_s0 + v*GCN_D + c0));
        const float4 b4 = *(const float4*)(smf + BS + c0);
        #pragma unroll
        for (int u = 0; u < V; u++) {
            int row = g*V + u;
            int m = RMKp[row];
            float4 s = make_float4(0.f, 0.f, 0.f, 0.f);
            #pragma unroll
            for (int v = 0; v < V; v++)
                if ((m >> v) & 1) { s.x += sv[v].x; s.y += sv[v].y; s.z += sv[v].z; s.w += sv[v].w; }
            const float4 g4 = *(const float4*)(smf + GS + RGIp[row]*GCN_D + c0);
            float y0 = fmaxf(g4.x*s.x + b4.x, 0.f);
            float y1 = fmaxf(g4.y*s.y + b4.y, 0.f);
            float y2 = fmaxf(g4.z*s.z + b4.z, 0.f);
            float y3 = fmaxf(g4.w*s.w + b4.w, 0.f);
            uint32_t h0 = dn2(y0, y1), h1 = dn2(y2, y3);
            float2 f0 = up2(h0), f1 = up2(h1);
            uint32_t l0 = dn2(y0 - f0.x, y1 - f0.y), l1 = dn2(y2 - f1.x, y3 - f1.y);
            *(uint2*)(smw + YPH + row*PST + (c0 >> 1)) = make_uint2(h0, h1);
            *(uint2*)(smw + YPL + row*PST + (c0 >> 1)) = make_uint2(l0, l1);
        }
    }

    // ----- layers 1..4 on tensor cores -----
    for (int li = 1; li < N_LAYERS; li++) {
        // AY pass: AP = A_aug @ Y (masked row sums), Y reconstructed hi+lo
        {
            const int g = ty, c0 = tx*4;
            float4 yv[V];
            #pragma unroll
            for (int v = 0; v < V; v++) {
                int row = g*V + v;
                uint2 h = *(const uint2*)(smw + YPH + row*PST + (c0 >> 1));
                uint2 l = *(const uint2*)(smw + YPL + row*PST + (c0 >> 1));
                float2 h0 = up2(h.x), h1 = up2(h.y), l0 = up2(l.x), l1 = up2(l.y);
                yv[v] = make_float4(h0.x + l0.x, h0.y + l0.y, h1.x + l1.x, h1.y + l1.y);
            }
            #pragma unroll
            for (int u = 0; u < V; u++) {
                int row = g*V + u;
                int m = RMKp[row];
                float s0 = 0.f, s1 = 0.f, s2 = 0.f, s3 = 0.f;
                #pragma unroll
                for (int v = 0; v < V; v++)
                    if ((m >> v) & 1) { s0 += yv[v].x; s1 += yv[v].y; s2 += yv[v].z; s3 += yv[v].w; }
                uint32_t h0 = dn2(s0, s1), h1 = dn2(s2, s3);
                float2 f0 = up2(h0), f1 = up2(h1);
                uint32_t l0 = dn2(s0 - f0.x, s1 - f0.y), l1 = dn2(s2 - f1.x, s3 - f1.y);
                *(uint2*)(smw + APH + row*PST + (c0 >> 1)) = make_uint2(h0, h1);
                *(uint2*)(smw + APL + row*PST + (c0 >> 1)) = make_uint2(l0, l1);
            }
        }
        __syncthreads();

        // GEMM: D(32x32 per warp) = AP @ W, 3-pass split bf16; W fragments from L2
        float d[2][4][4];
        #pragma unroll
        for (int mt = 0; mt < 2; mt++)
            #pragma unroll
            for (int nt = 0; nt < 4; nt++)
                #pragma unroll
                for (int j = 0; j < 4; j++) d[mt][nt][j] = 0.f;

        const uint32_t* WH = g_WPh + (size_t)(li-1)*GCN_D*WST;
        const uint32_t* WL = g_WPl + (size_t)(li-1)*GCN_D*WST;

        #pragma unroll 2
        for (int kt = 0; kt < 8; kt++) {
            const int kb = kt*8 + tq;
            uint32_t ah[2][4], al[2][4], bh[4][2], bl[4][2];
            #pragma unroll
            for (int nt = 0; nt < 4; nt++) {
                int rn = (nw*32 + nt*8 + gq)*WST + kb;
                bh[nt][0] = __ldg(WH + rn); bh[nt][1] = __ldg(WH + rn + 4);
                bl[nt][0] = __ldg(WL + rn); bl[nt][1] = __ldg(WL + rn + 4);
            }
            #pragma unroll
            for (int mt = 0; mt < 2; mt++) {
                int r0 = (mw*32 + mt*16 + gq)*PST + kb;
                int r1 = r0 + 8*PST;
                ah[mt][0] = smw[APH + r0];     ah[mt][1] = smw[APH + r1];
                ah[mt][2] = smw[APH + r0 + 4]; ah[mt][3] = smw[APH + r1 + 4];
                al[mt][0] = smw[APL + r0];     al[mt][1] = smw[APL + r1];
                al[mt][2] = smw[APL + r0 + 4]; al[mt][3] = smw[APL + r1 + 4];
            }
            #pragma unroll
            for (int mt = 0; mt < 2; mt++)
                #pragma unroll
                for (int nt = 0; nt < 4; nt++) {
                    mma16816(d[mt][nt], ah[mt], bh[nt]);
                    mma16816(d[mt][nt], al[mt], bh[nt]);
                    mma16816(d[mt][nt], ah[mt], bl[nt]);
                }
        }

        // pointwise epilogue: y = gate*d + b (+relu), write packed hi/lo Y
        const bool last = (li == N_LAYERS - 1);
        #pragma unroll
        for (int mt = 0; mt < 2; mt++) {
            #pragma unroll
            for (int nt = 0; nt < 4; nt++) {
                int R = mw*32 + mt*16 + gq;
                int C = nw*32 + nt*8 + 2*tq;
                float2 g0 = *(const float2*)(smf + GS + li*6*GCN_D + RGIp[R]*GCN_D + C);
                float2 g1 = *(const float2*)(smf + GS + li*6*GCN_D + RGIp[R+8]*GCN_D + C);
                float2 bb = *(const float2*)(smf + BS + li*GCN_D + C);
                float y0 = g0.x*d[mt][nt][0] + bb.x;
                float y1 = g0.y*d[mt][nt][1] + bb.y;
                float y2 = g1.x*d[mt][nt][2] + bb.x;
                float y3 = g1.y*d[mt][nt][3] + bb.y;
                if (!last) {
                    y0 = fmaxf(y0, 0.f); y1 = fmaxf(y1, 0.f);
                    y2 = fmaxf(y2, 0.f); y3 = fmaxf(y3, 0.f);
                }
                uint32_t h0 = dn2(y0, y1), h1 = dn2(y2, y3);
                float2 f0 = up2(h0), f1 = up2(h1);
                uint32_t l0 = dn2(y0 - f0.x, y1 - f0.y), l1 = dn2(y2 - f1.x, y3 - f1.y);
                smw[YPH + R*PST + (C >> 1)]     = h0;
                smw[YPL + R*PST + (C >> 1)]     = l0;
                smw[YPH + (R+8)*PST + (C >> 1)] = h1;
                smw[YPL + (R+8)*PST + (C >> 1)] = l1;
            }
        }
        __syncthreads();
    }

    // ----- readout: z[g] = sum_u rw[u] * Y[g*7+u] -----
    {
        const int g = ty, c0 = tx*4;
        float4 z = make_float4(0.f, 0.f, 0.f, 0.f);
        #pragma unroll
        for (int u = 0; u < V; u++) {
            int row = g*V + u;
            float rw = RRDp[row];
            uint2 h = *(const uint2*)(smw + YPH + row*PST + (c0 >> 1));
            uint2 l = *(const uint2*)(smw + YPL + row*PST + (c0 >> 1));
            float2 h0 = up2(h.x), h1 = up2(h.y), l0 = up2(l.x), l1 = up2(l.y);
            z.x += rw*(h0.x + l0.x); z.y += rw*(h0.y + l0.y);
            z.z += rw*(h1.x + l1.x); z.w += rw*(h1.y + l1.y);
        }
        *(float4*)(smf + ZS + g*132 + c0) = z;
    }

    // ----- MLP: one warp per graph (reads own-warp Z, no barrier needed) -----
    {
        const float* zrow = smf + ZS + ty*132;
        float accm[7];
        #pragma unroll
        for (int c = 0; c < 7; c++) accm[c] = 0.f;
        for (int k = 0; k < GCN_D; k++) {
            float zk = zrow[k];
            const float* w1p = mlp_w1 + (size_t)k*MLP_H + tx;
            #pragma unroll
            for (int c = 0; c < 7; c++) {
                int j = tx + 32*c;
                if (j < MLP_H) accm[c] = fmaf(zk, __ldg(w1p + 32*c), accm[c]);
            }
        }
        float part = 0.f;
        #pragma unroll
        for (int c = 0; c < 7; c++) {
            int j = tx + 32*c;
            if (j < MLP_H) part += fmaxf(accm[c] + mlp_b1[j], 0.f) * mlp_w2[j];
        }
        #pragma unroll
        for (int o = 16; o > 0; o >>= 1) part += __shfl_down_sync(0xffffffffu, part, o);
        if (tx == 0 && (gbase + ty) < Btot) out[gbase + ty] = part + mlp_b2[0];
    }
}

extern "C" void kernel_launch(void* const* d_in, const int* in_sizes, int n_in,
                              void* d_out, int out_size)
{
    const float* adjs           = (const float*)d_in[0];
    const int*   op_inds        = (const int*)  d_in[1];
    const float* input_node_emb = (const float*)d_in[2];
    const float* other_node_emb = (const float*)d_in[3];
    const float* input_op_emb   = (const float*)d_in[4];
    const float* op_emb_table   = (const float*)d_in[5];
    const float* output_op_emb  = (const float*)d_in[6];
    const float* xh_w           = (const float*)d_in[7];
    const float* xh_b           = (const float*)d_in[8];
    const float* gcn0_w         = (const float*)d_in[9];
    const float* gcn_w          = (const float*)d_in[10];
    const float* attn_w         = (const float*)d_in[11];
    const float* attn_b         = (const float*)d_in[12];
    const float* gcn_b          = (const float*)d_in[13];
    const float* mlp_w1         = (const float*)d_in[14];
    const float* mlp_b1         = (const float*)d_in[15];
    const float* mlp_w2         = (const float*)d_in[16];
    const float* mlp_b2         = (const float*)d_in[17];
    float* out = (float*)d_out;

    int Btot = in_sizes[0] / (V*V);

    precompute_kernel<<<1, 256>>>(input_node_emb, other_node_emb, input_op_emb,
                                  op_emb_table, output_op_emb, xh_w, xh_b,
                                  gcn0_w, attn_w, attn_b);
    prep_w_kernel<<<((N_LAYERS-1)*GCN_D*WST + 255)/256, 256>>>(gcn_w);

    size_t smem = SMEM_WORDS * sizeof(uint32_t);
    cudaFuncSetAttribute(nb101_main, cudaFuncAttributeMaxDynamicSharedMemorySize, (int)smem);
    int grid = (Btot + G - 1) / G;
    nb101_main<<<grid, NTHREADS, smem>>>(adjs, op_inds, gcn_b,
                                         mlp_w1, mlp_b1, mlp_w2, mlp_b2, out, Btot);
}

// round 12
// speedup vs baseline: 2.0039x; 2.0039x over previous
#include <cuda_runtime.h>
#include <cuda_bf16.h>
#include <math.h>
#include <stdint.h>

#define V 7
#define NODE_D 48
#define OP_D 48
#define HID 96
#define GCN_D 128
#define N_LAYERS 5
#define MLP_H 200
#define NONE_OP 3

#define G 16             // graphs per CTA -> 112 real rows of a 128-row GEMM
#define NTHREADS 512     // 16 warps
#define YST 132          // fp32 Y stride (words)
#define PST 68           // packed bf16-pair stride (u32 words per row)
#define W1ST 64          // packed w1 fragment stride

// ---- shared memory word (u32) offsets ----
#define APH 0                      // A hi pairs: 128*68
#define APL (APH + 128*PST)        // 8704
#define WPH (APL + 128*PST)        // 17408
#define WPL (WPH + 128*PST)        // 26112
#define YS  (WPL + 128*PST)        // 34816 : fp32 Y 128*132 = 16896
#define GS  (YS + 128*YST)         // 51712 : gates 5*6*128 = 3840
#define BS  (GS + N_LAYERS*6*GCN_D)// 55552 : biases 5*128 = 640
#define RMK (BS + N_LAYERS*GCN_D)  // 56192
#define RGI (RMK + 128)            // 56320
#define RRD (RGI + 128)            // 56448
#define PART (RRD + 128)           // 56576 : MLP partials 16x16
#define SMEM_WORDS (PART + 256)    // 56832 words = 227328 B

typedef unsigned long long ull;

// Precomputed, batch-independent tables
__device__ float g_s0[V*GCN_D];
__device__ float g_gate[N_LAYERS*6*GCN_D];
__device__ uint32_t g_WPh[(N_LAYERS-1)*128*PST];  // W hi, fragment layout [n][kpair] (PST-padded)
__device__ uint32_t g_WPl[(N_LAYERS-1)*128*PST];  // W lo
__device__ uint32_t g_W1h[256*W1ST];              // mlp_w1 hi fragments [n][kpair]
__device__ uint32_t g_W1l[256*W1ST];              // mlp_w1 lo

__device__ __forceinline__ void mma16816(float* d, const uint32_t* a, const uint32_t* b) {
    asm volatile("mma.sync.aligned.m16n8k16.row.col.f32.bf16.bf16.f32 "
        "{%0,%1,%2,%3}, {%4,%5,%6,%7}, {%8,%9}, {%0,%1,%2,%3};"
        : "+f"(d[0]), "+f"(d[1]), "+f"(d[2]), "+f"(d[3])
        : "r"(a[0]), "r"(a[1]), "r"(a[2]), "r"(a[3]), "r"(b[0]), "r"(b[1]));
}
__device__ __forceinline__ uint32_t smem_u32(const void* p) {
    uint32_t a;
    asm("{ .reg .u64 t; cvta.to.shared.u64 t, %1; cvt.u32.u64 %0, t; }" : "=r"(a) : "l"(p));
    return a;
}
__device__ __forceinline__ void cpa16(uint32_t dst, const void* src) {
    asm volatile("cp.async.cg.shared.global [%0], [%1], 16;" :: "r"(dst), "l"(src));
}
__device__ __forceinline__ void unpack2(ull v, float& x, float& y) {
    asm("mov.b64 {%0, %1}, %2;" : "=f"(x), "=f"(y) : "l"(v));
}
__device__ __forceinline__ ull pack2(float x, float y) {
    ull r; asm("mov.b64 %0, {%1, %2};" : "=l"(r) : "f"(x), "f"(y)); return r;
}
__device__ __forceinline__ void add2(ull& d, ull a, ull b) {
    asm("add.rn.f32x2 %0, %1, %2;" : "=l"(d) : "l"(a), "l"(b));
}
__device__ __forceinline__ void fma2(ull& d, ull a, ull b, ull c) {
    asm("fma.rn.f32x2 %0, %1, %2, %3;" : "=l"(d) : "l"(a), "l"(b), "l"(c));
}

__global__ void precompute_kernel(
    const float* __restrict__ input_node_emb,
    const float* __restrict__ other_node_emb,
    const float* __restrict__ input_op_emb,
    const float* __restrict__ op_emb_table,
    const float* __restrict__ output_op_emb,
    const float* __restrict__ xh_w,
    const float* __restrict__ xh_b,
    const float* __restrict__ gcn0_w,
    const float* __restrict__ attn_w,
    const float* __restrict__ attn_b)
{
    __shared__ float y0[2][HID];
    int t = threadIdx.x;
    if (t < 2*HID) {
        int r = t / HID, c = t % HID;
        const float* e = (r == 0) ? input_node_emb : other_node_emb;
        float acc = xh_b[c];
        for (int d = 0; d < NODE_D; d++) acc += e[d] * xh_w[d*HID + c];
        y0[r][c] = acc;
    }
    __syncthreads();
    for (int idx = t; idx < V*GCN_D; idx += blockDim.x) {
        int v = idx / GCN_D, n = idx % GCN_D;
        const float* yr = y0[(v == 0) ? 0 : 1];
        float acc = 0.f;
        for (int d = 0; d < HID; d++) acc += yr[d] * gcn0_w[d*GCN_D + n];
        g_s0[idx] = acc;
    }
    for (int idx = t; idx < N_LAYERS*6*GCN_D; idx += blockDim.x) {
        int i = idx / (6*GCN_D);
        int r = idx % (6*GCN_D);
        int gi = r / GCN_D, n = r % GCN_D;
        const float* e = (gi == 0) ? input_op_emb
                       : (gi <= 4 ? op_emb_table + (gi-1)*OP_D : output_op_emb);
        float acc = attn_b[i*GCN_D + n];
        for (int d = 0; d < OP_D; d++) acc += e[d] * attn_w[(i*OP_D + d)*GCN_D + n];
        g_gate[idx] = 1.f / (1.f + expf(-acc));
    }
}

// Pack gcn_w into mma B-fragment layout: [n][kpair], hi/lo split, PST-padded rows.
__global__ void prep_w_kernel(const float* __restrict__ gcn_w) {
    int idx = blockIdx.x * blockDim.x + threadIdx.x;
    if (idx >= (N_LAYERS-1)*GCN_D*64) return;
    int li = idx >> 13;
    int r  = idx & 8191;
    int n  = r >> 6, kp = r & 63;
    const float* wl = gcn_w + (size_t)li*GCN_D*GCN_D;
    float w0 = wl[(2*kp)*GCN_D + n];
    float w1 = wl[(2*kp+1)*GCN_D + n];
    __nv_bfloat162 h = __floats2bfloat162_rn(w0, w1);
    __nv_bfloat162 l = __floats2bfloat162_rn(w0 - __bfloat162float(h.x),
                                             w1 - __bfloat162float(h.y));
    int o = li*128*PST + n*PST + kp;
    g_WPh[o] = *(uint32_t*)&h;
    g_WPl[o] = *(uint32_t*)&l;
}

// Pack mlp_w1 into fragment layout [n(256, zero-pad >=200)][kpair], hi/lo.
__global__ void prep_w1_kernel(const float* __restrict__ mlp_w1) {
    int idx = blockIdx.x * blockDim.x + threadIdx.x;
    if (idx >= 256*W1ST) return;
    int n = idx >> 6, kp = idx & 63;
    float w0 = 0.f, w1 = 0.f;
    if (n < MLP_H) {
        w0 = mlp_w1[(2*kp)*MLP_H + n];
        w1 = mlp_w1[(2*kp+1)*MLP_H + n];
    }
    __nv_bfloat162 h = __floats2bfloat162_rn(w0, w1);
    __nv_bfloat162 l = __floats2bfloat162_rn(w0 - __bfloat162float(h.x),
                                             w1 - __bfloat162float(h.y));
    g_W1h[idx] = *(uint32_t*)&h;
    g_W1l[idx] = *(uint32_t*)&l;
}

__global__ __launch_bounds__(NTHREADS, 1) void nb101_main(
    const float* __restrict__ adjs,
    const int*   __restrict__ op_inds,
    const float* __restrict__ gcn_b,
    const float* __restrict__ mlp_b1,
    const float* __restrict__ mlp_w2,
    const float* __restrict__ mlp_b2,
    float* __restrict__ out,
    int Btot)
{
    extern __shared__ uint32_t smw[];
    float* smf = (float*)smw;
    int*   RMKp = (int*)(smw + RMK);
    int*   RGIp = (int*)(smw + RGI);
    float* RRDp = (float*)(smw + RRD);

    const uint32_t smem_base = smem_u32(smw);
    const int t  = threadIdx.x;
    const int tx = t & 31;
    const int ty = t >> 5;           // warp id 0..15
    const int gq = tx >> 2;          // mma group id (0..7)
    const int tq = tx & 3;           // thread-in-group
    const int mw = ty >> 2;          // warp m-tile (rows mw*32)
    const int nw = ty & 3;           // warp n-tile (cols nw*32)
    const int gbase = blockIdx.x * G;

    // kick off async copy of layer-1 W fragments into smem (overlaps everything below)
    {
        const uint4* srcH = (const uint4*)(g_WPh);
        const uint4* srcL = (const uint4*)(g_WPl);
        uint32_t dH = smem_base + WPH*4;
        uint32_t dL = smem_base + WPL*4;
        for (int i = t; i < 128*PST/4; i += NTHREADS) {
            cpa16(dH + i*16, srcH + i);
            cpa16(dL + i*16, srcL + i);
        }
        asm volatile("cp.async.commit_group;" ::: "memory");
    }

    // stage gate/bias tables
    for (int i = t; i < N_LAYERS*6*GCN_D; i += NTHREADS) smf[GS + i] = g_gate[i];
    for (int i = t; i < N_LAYERS*GCN_D;   i += NTHREADS) smf[BS + i] = gcn_b[i];

    // per-row metadata (rows 0..111 real, 112..127 pad)
    if (t < 128) {
        int m = 0, gi = 0; float rw = 0.f;
        if (t < G*V) {
            int g = t / V, u = t - g*V;
            int batch = gbase + g;
            if (batch < Btot) {
                const float* arow = adjs + (size_t)batch*(V*V) + u*V;
                m = 1 << u;
                #pragma unroll
                for (int v2 = 0; v2 < V; v2++) if (arow[v2] != 0.f) m |= 1 << v2;
                if (u == 0)        { gi = 0; rw = 0.f; }
                else if (u == V-1) { gi = 5; rw = 1.f/6.f; }
                else {
                    int op = op_inds[(size_t)batch*(V-2) + (u-1)];
                    gi = 1 + op;
                    rw = (op != NONE_OP) ? (1.f/6.f) : 0.f;
                }
            }
        }
        RMKp[t] = m; RGIp[t] = gi; RRDp[t] = rw;
    }
    __syncthreads();

    // ----- layer 0: Y1 = relu(gate0 * (A_aug @ S0) + b0) -> Ysm fp32 -----
    {
        const int g = ty, c0 = tx*4;
        float4 sv[V];
        #pragma unroll
        for (int v = 0; v < V; v++) sv[v] = __ldg((const float4*)(g_s0 + v*GCN_D + c0));
        const float4 b4 = *(const float4*)(smf + BS + c0);
        #pragma unroll
        for (int u = 0; u < V; u++) {
            int row = g*V + u;
            int m = RMKp[row];
            float4 s = make_float4(0.f, 0.f, 0.f, 0.f);
            #pragma unroll
            for (int v = 0; v < V; v++)
                if ((m >> v) & 1) { s.x += sv[v].x; s.y += sv[v].y; s.z += sv[v].z; s.w += sv[v].w; }
            const float4 g4 = *(const float4*)(smf + GS + RGIp[row]*GCN_D + c0);
            float4 y;
            y.x = fmaxf(g4.x*s.x + b4.x, 0.f);
            y.y = fmaxf(g4.y*s.y + b4.y, 0.f);
            y.z = fmaxf(g4.z*s.z + b4.z, 0.f);
            y.w = fmaxf(g4.w*s.w + b4.w, 0.f);
            *(float4*)(smf + YS + row*YST + c0) = y;
        }
    }
    __syncthreads();

    // ----- layers 1..4 on tensor cores -----
    for (int li = 1; li < N_LAYERS; li++) {
        // issue async copy of this layer's W (layer 1 already in flight from entry)
        if (li > 1) {
            const uint4* srcH = (const uint4*)(g_WPh + (size_t)(li-1)*128*PST);
            const uint4* srcL = (const uint4*)(g_WPl + (size_t)(li-1)*128*PST);
            uint32_t dH = smem_base + WPH*4;
            uint32_t dL = smem_base + WPL*4;
            for (int i = t; i < 128*PST/4; i += NTHREADS) {
                cpa16(dH + i*16, srcH + i);
                cpa16(dL + i*16, srcL + i);
            }
            asm volatile("cp.async.commit_group;" ::: "memory");
        }

        // AY pass: AP = A_aug @ Y (masked row sums, packed f32x2), split bf16 hi/lo
        {
            const int g = ty, c0 = tx*4;
            ulonglong2 yv[V];
            #pragma unroll
            for (int v = 0; v < V; v++)
                yv[v] = *(const ulonglong2*)(smf + YS + (g*V + v)*YST + c0);
            #pragma unroll
            for (int u = 0; u < V; u++) {
                int row = g*V + u;
                int m = RMKp[row];
                ull s01 = 0ull, s23 = 0ull;
                #pragma unroll
                for (int v = 0; v < V; v++)
                    if ((m >> v) & 1) { add2(s01, s01, yv[v].x); add2(s23, s23, yv[v].y); }
                float s0, s1, s2, s3;
                unpack2(s01, s0, s1); unpack2(s23, s2, s3);
                __nv_bfloat162 hA = __floats2bfloat162_rn(s0, s1);
                __nv_bfloat162 hB = __floats2bfloat162_rn(s2, s3);
                __nv_bfloat162 lA = __floats2bfloat162_rn(s0 - __bfloat162float(hA.x),
                                                          s1 - __bfloat162float(hA.y));
                __nv_bfloat162 lB = __floats2bfloat162_rn(s2 - __bfloat162float(hB.x),
                                                          s3 - __bfloat162float(hB.y));
                *(uint2*)(smw + APH + row*PST + (c0 >> 1)) = make_uint2(*(uint32_t*)&hA, *(uint32_t*)&hB);
                *(uint2*)(smw + APL + row*PST + (c0 >> 1)) = make_uint2(*(uint32_t*)&lA, *(uint32_t*)&lB);
            }
        }
        asm volatile("cp.async.wait_group 0;" ::: "memory");
        __syncthreads();

        // GEMM: D(32x32 per warp) = AP @ WP, 3-pass split bf16
        float d[2][4][4];
        #pragma unroll
        for (int mt = 0; mt < 2; mt++)
            #pragma unroll
            for (int nt = 0; nt < 4; nt++)
                #pragma unroll
                for (int j = 0; j < 4; j++) d[mt][nt][j] = 0.f;

        #pragma unroll 2
        for (int kt = 0; kt < 8; kt++) {
            const int kb = kt*8 + tq;
            uint32_t ah[2][4], al[2][4], bh[4][2], bl[4][2];
            #pragma unroll
            for (int mt = 0; mt < 2; mt++) {
                int r0 = (mw*32 + mt*16 + gq)*PST + kb;
                int r1 = r0 + 8*PST;
                ah[mt][0] = smw[APH + r0];     ah[mt][1] = smw[APH + r1];
                ah[mt][2] = smw[APH + r0 + 4]; ah[mt][3] = smw[APH + r1 + 4];
                al[mt][0] = smw[APL + r0];     al[mt][1] = smw[APL + r1];
                al[mt][2] = smw[APL + r0 + 4]; al[mt][3] = smw[APL + r1 + 4];
            }
            #pragma unroll
            for (int nt = 0; nt < 4; nt++) {
                int rn = (nw*32 + nt*8 + gq)*PST + kb;
                bh[nt][0] = smw[WPH + rn]; bh[nt][1] = smw[WPH + rn + 4];
                bl[nt][0] = smw[WPL + rn]; bl[nt][1] = smw[WPL + rn + 4];
            }
            #pragma unroll
            for (int mt = 0; mt < 2; mt++)
                #pragma unroll
                for (int nt = 0; nt < 4; nt++) {
                    mma16816(d[mt][nt], ah[mt], bh[nt]);
                    mma16816(d[mt][nt], al[mt], bh[nt]);
                    mma16816(d[mt][nt], ah[mt], bl[nt]);
                }
        }

        // pointwise epilogue: y = gate*d + b (+relu), write fp32 Y
        const bool last = (li == N_LAYERS - 1);
        #pragma unroll
        for (int mt = 0; mt < 2; mt++) {
            #pragma unroll
            for (int nt = 0; nt < 4; nt++) {
                int R = mw*32 + mt*16 + gq;
                int C = nw*32 + nt*8 + 2*tq;
                float2 g0 = *(const float2*)(smf + GS + li*6*GCN_D + RGIp[R]*GCN_D + C);
                float2 g1 = *(const float2*)(smf + GS + li*6*GCN_D + RGIp[R+8]*GCN_D + C);
                float2 bb = *(const float2*)(smf + BS + li*GCN_D + C);
                float y0 = g0.x*d[mt][nt][0] + bb.x;
                float y1 = g0.y*d[mt][nt][1] + bb.y;
                float y2 = g1.x*d[mt][nt][2] + bb.x;
                float y3 = g1.y*d[mt][nt][3] + bb.y;
                if (!last) {
                    y0 = fmaxf(y0, 0.f); y1 = fmaxf(y1, 0.f);
                    y2 = fmaxf(y2, 0.f); y3 = fmaxf(y3, 0.f);
                }
                *(float2*)(smf + YS + R*YST + C)     = make_float2(y0, y1);
                *(float2*)(smf + YS + (R+8)*YST + C) = make_float2(y2, y3);
            }
        }
        __syncthreads();
    }

    // ----- readout: z[g] packed into APH/APL rows 0..15 (a-frag layout for MLP MMA) -----
    {
        const int g = ty, c0 = tx*4;
        ull z01 = 0ull, z23 = 0ull;
        #pragma unroll
        for (int u = 0; u < V; u++) {
            int row = g*V + u;
            float rw = RRDp[row];
            ull rp = pack2(rw, rw);
            ulonglong2 yv = *(const ulonglong2*)(smf + YS + row*YST + c0);
            fma2(z01, rp, yv.x, z01);
            fma2(z23, rp, yv.y, z23);
        }
        float z0, z1, z2, z3;
        unpack2(z01, z0, z1); unpack2(z23, z2, z3);
        __nv_bfloat162 hA = __floats2bfloat162_rn(z0, z1);
        __nv_bfloat162 hB = __floats2bfloat162_rn(z2, z3);
        __nv_bfloat162 lA = __floats2bfloat162_rn(z0 - __bfloat162float(hA.x),
                                                  z1 - __bfloat162float(hA.y));
        __nv_bfloat162 lB = __floats2bfloat162_rn(z2 - __bfloat162float(hB.x),
                                                  z3 - __bfloat162float(hB.y));
        *(uint2*)(smw + APH + g*PST + (c0 >> 1)) = make_uint2(*(uint32_t*)&hA, *(uint32_t*)&hB);
        *(uint2*)(smw + APL + g*PST + (c0 >> 1)) = make_uint2(*(uint32_t*)&lA, *(uint32_t*)&lB);
    }
    __syncthreads();

    // ----- MLP layer 1 via MMA: h(16 x 256pad) = z @ w1; fold relu+w2 reduction -----
    {
        float d[2][4];
        #pragma unroll
        for (int nt = 0; nt < 2; nt++)
            #pragma unroll
            for (int j = 0; j < 4; j++) d[nt][j] = 0.f;

        #pragma unroll 2
        for (int kt = 0; kt < 8; kt++) {
            const int kb = kt*8 + tq;
            uint32_t ah[4], al[4], bh[2][2], bl[2][2];
            int r0 = gq*PST + kb;
            int r1 = r0 + 8*PST;
            ah[0] = smw[APH + r0];     ah[1] = smw[APH + r1];
            ah[2] = smw[APH + r0 + 4]; ah[3] = smw[APH + r1 + 4];
            al[0] = smw[APL + r0];     al[1] = smw[APL + r1];
            al[2] = smw[APL + r0 + 4]; al[3] = smw[APL + r1 + 4];
            #pragma unroll
            for (int nt = 0; nt < 2; nt++) {
                int rn = (ty*16 + nt*8 + gq)*W1ST + kb;
                bh[nt][0] = __ldg(g_W1h + rn); bh[nt][1] = __ldg(g_W1h + rn + 4);
                bl[nt][0] = __ldg(g_W1l + rn); bl[nt][1] = __ldg(g_W1l + rn + 4);
            }
            #pragma unroll
            for (int nt = 0; nt < 2; nt++) {
                mma16816(d[nt], ah, bh[nt]);
                mma16816(d[nt], al, bh[nt]);
                mma16816(d[nt], ah, bl[nt]);
            }
        }

        // bias + relu + w2 scale; partial sums for graphs gq (rows 0-7) and gq+8
        float p0 = 0.f, p1 = 0.f;
        #pragma unroll
        for (int nt = 0; nt < 2; nt++) {
            int C = ty*16 + nt*8 + 2*tq;
            #pragma unroll
            for (int e = 0; e < 2; e++) {
                int j = C + e;
                if (j < MLP_H) {
                    float b1v = __ldg(mlp_b1 + j);
                    float w2v = __ldg(mlp_w2 + j);
                    p0 += fmaxf(d[nt][e]     + b1v, 0.f) * w2v;
                    p1 += fmaxf(d[nt][2 + e] + b1v, 0.f) * w2v;
                }
            }
        }
        p0 += __shfl_down_sync(0xffffffffu, p0, 1);
        p0 += __shfl_down_sync(0xffffffffu, p0, 2);
        p1 += __shfl_down_sync(0xffffffffu, p1, 1);
        p1 += __shfl_down_sync(0xffffffffu, p1, 2);
        if (tq == 0) {
            smf[PART + gq*16 + ty]       = p0;
            smf[PART + (gq + 8)*16 + ty] = p1;
        }
    }
    __syncthreads();

    if (t < G) {
        float s = 0.f;
        #pragma unroll
        for (int w = 0; w < 16; w++) s += smf[PART + t*16 + w];
        if (gbase + t < Btot) out[gbase + t] = s + __ldg(mlp_b2);
    }
}

extern "C" void kernel_launch(void* const* d_in, const int* in_sizes, int n_in,
                              void* d_out, int out_size)
{
    const float* adjs           = (const float*)d_in[0];
    const int*   op_inds        = (const int*)  d_in[1];
    const float* input_node_emb = (const float*)d_in[2];
    const float* other_node_emb = (const float*)d_in[3];
    const float* input_op_emb   = (const float*)d_in[4];
    const float* op_emb_table   = (const float*)d_in[5];
    const float* output_op_emb  = (const float*)d_in[6];
    const float* xh_w           = (const float*)d_in[7];
    const float* xh_b           = (const float*)d_in[8];
    const float* gcn0_w         = (const float*)d_in[9];
    const float* gcn_w          = (const float*)d_in[10];
    const float* attn_w         = (const float*)d_in[11];
    const float* attn_b         = (const float*)d_in[12];
    const float* gcn_b          = (const float*)d_in[13];
    const float* mlp_w1         = (const float*)d_in[14];
    const float* mlp_b1         = (const float*)d_in[15];
    const float* mlp_w2         = (const float*)d_in[16];
    const float* mlp_b2         = (const float*)d_in[17];
    float* out = (float*)d_out;

    int Btot = in_sizes[0] / (V*V);

    precompute_kernel<<<1, 256>>>(input_node_emb, other_node_emb, input_op_emb,
                                  op_emb_table, output_op_emb, xh_w, xh_b,
                                  gcn0_w, attn_w, attn_b);
    prep_w_kernel<<<((N_LAYERS-1)*GCN_D*64 + 255)/256, 256>>>(gcn_w);
    prep_w1_kernel<<<(256*W1ST + 255)/256, 256>>>(mlp_w1);

    size_t smem = SMEM_WORDS * sizeof(uint32_t);
    cudaFuncSetAttribute(nb101_main, cudaFuncAttributeMaxDynamicSharedMemorySize, (int)smem);
    int grid = (Btot + G - 1) / G;
    nb101_main<<<grid, NTHREADS, smem>>>(adjs, op_inds, gcn_b,
                                         mlp_b1, mlp_w2, mlp_b2, out, Btot);
}

// round 13
// speedup vs baseline: 2.0469x; 1.0214x over previous
#include <cuda_runtime.h>
#include <cuda_bf16.h>
#include <math.h>
#include <stdint.h>

#define V 7
#define NODE_D 48
#define OP_D 48
#define HID 96
#define GCN_D 128
#define N_LAYERS 5
#define MLP_H 200
#define NONE_OP 3

#define G 16             // graphs per CTA -> 112 real rows of a 128-row GEMM
#define NTHREADS 1024    // 32 warps: 8 m-tiles x 4 n-tiles of 16x32
#define YST 132          // fp32 Y stride (words)
#define PST 68           // packed bf16-pair stride (u32 words per row)
#define W1ST 64          // packed w1 fragment stride

// ---- shared memory word (u32) offsets ----
#define APH 0                      // A hi pairs: 128*68
#define APL (APH + 128*PST)        // 8704
#define WPH (APL + 128*PST)        // 17408
#define WPL (WPH + 128*PST)        // 26112
#define YS  (WPL + 128*PST)        // 34816 : fp32 Y 128*132 = 16896
#define GS  (YS + 128*YST)         // 51712 : gates 5*6*128 = 3840
#define BS  (GS + N_LAYERS*6*GCN_D)// 55552 : biases 5*128 = 640
#define RMK (BS + N_LAYERS*GCN_D)  // 56192
#define RGI (RMK + 128)            // 56320
#define RRD (RGI + 128)            // 56448
#define PART (RRD + 128)           // 56576 : MLP partials 16 graphs x 32 warps
#define SMEM_WORDS (PART + 512)    // 57088 words = 228352 B

typedef unsigned long long ull;

// Precomputed, batch-independent tables
__device__ float g_s0[V*GCN_D];
__device__ float g_gate[N_LAYERS*6*GCN_D];
__device__ uint32_t g_WPh[(N_LAYERS-1)*128*PST];  // W hi, fragment layout [n][kpair] (PST-padded)
__device__ uint32_t g_WPl[(N_LAYERS-1)*128*PST];  // W lo
__device__ uint32_t g_W1h[256*W1ST];              // mlp_w1 hi fragments [n][kpair]
__device__ uint32_t g_W1l[256*W1ST];              // mlp_w1 lo

__device__ __forceinline__ void mma16816(float* d, const uint32_t* a, const uint32_t* b) {
    asm volatile("mma.sync.aligned.m16n8k16.row.col.f32.bf16.bf16.f32 "
        "{%0,%1,%2,%3}, {%4,%5,%6,%7}, {%8,%9}, {%0,%1,%2,%3};"
        : "+f"(d[0]), "+f"(d[1]), "+f"(d[2]), "+f"(d[3])
        : "r"(a[0]), "r"(a[1]), "r"(a[2]), "r"(a[3]), "r"(b[0]), "r"(b[1]));
}
__device__ __forceinline__ void ldsm4(uint32_t* r, uint32_t addr) {
    asm volatile("ldmatrix.sync.aligned.m8n8.x4.shared.b16 {%0,%1,%2,%3}, [%4];"
        : "=r"(r[0]), "=r"(r[1]), "=r"(r[2]), "=r"(r[3]) : "r"(addr));
}
__device__ __forceinline__ uint32_t smem_u32(const void* p) {
    uint32_t a;
    asm("{ .reg .u64 t; cvta.to.shared.u64 t, %1; cvt.u32.u64 %0, t; }" : "=r"(a) : "l"(p));
    return a;
}
__device__ __forceinline__ void cpa16(uint32_t dst, const void* src) {
    asm volatile("cp.async.cg.shared.global [%0], [%1], 16;" :: "r"(dst), "l"(src));
}

__global__ void precompute_kernel(
    const float* __restrict__ input_node_emb,
    const float* __restrict__ other_node_emb,
    const float* __restrict__ input_op_emb,
    const float* __restrict__ op_emb_table,
    const float* __restrict__ output_op_emb,
    const float* __restrict__ xh_w,
    const float* __restrict__ xh_b,
    const float* __restrict__ gcn0_w,
    const float* __restrict__ attn_w,
    const float* __restrict__ attn_b)
{
    __shared__ float y0[2][HID];
    int t = threadIdx.x;
    if (t < 2*HID) {
        int r = t / HID, c = t % HID;
        const float* e = (r == 0) ? input_node_emb : other_node_emb;
        float acc = xh_b[c];
        for (int d = 0; d < NODE_D; d++) acc += e[d] * xh_w[d*HID + c];
        y0[r][c] = acc;
    }
    __syncthreads();
    for (int idx = t; idx < V*GCN_D; idx += blockDim.x) {
        int v = idx / GCN_D, n = idx % GCN_D;
        const float* yr = y0[(v == 0) ? 0 : 1];
        float acc = 0.f;
        for (int d = 0; d < HID; d++) acc += yr[d] * gcn0_w[d*GCN_D + n];
        g_s0[idx] = acc;
    }
    for (int idx = t; idx < N_LAYERS*6*GCN_D; idx += blockDim.x) {
        int i = idx / (6*GCN_D);
        int r = idx % (6*GCN_D);
        int gi = r / GCN_D, n = r % GCN_D;
        const float* e = (gi == 0) ? input_op_emb
                       : (gi <= 4 ? op_emb_table + (gi-1)*OP_D : output_op_emb);
        float acc = attn_b[i*GCN_D + n];
        for (int d = 0; d < OP_D; d++) acc += e[d] * attn_w[(i*OP_D + d)*GCN_D + n];
        g_gate[idx] = 1.f / (1.f + expf(-acc));
    }
}

// Pack gcn_w into mma B-fragment layout: [n][kpair], hi/lo split, PST-padded rows.
__global__ void prep_w_kernel(const float* __restrict__ gcn_w) {
    int idx = blockIdx.x * blockDim.x + threadIdx.x;
    if (idx >= (N_LAYERS-1)*GCN_D*64) return;
    int li = idx >> 13;
    int r  = idx & 8191;
    int n  = r >> 6, kp = r & 63;
    const float* wl = gcn_w + (size_t)li*GCN_D*GCN_D;
    float w0 = wl[(2*kp)*GCN_D + n];
    float w1 = wl[(2*kp+1)*GCN_D + n];
    __nv_bfloat162 h = __floats2bfloat162_rn(w0, w1);
    __nv_bfloat162 l = __floats2bfloat162_rn(w0 - __bfloat162float(h.x),
                                             w1 - __bfloat162float(h.y));
    int o = li*128*PST + n*PST + kp;
    g_WPh[o] = *(uint32_t*)&h;
    g_WPl[o] = *(uint32_t*)&l;
}

// Pack mlp_w1 into fragment layout [n(256, zero-pad >=200)][kpair], hi/lo.
__global__ void prep_w1_kernel(const float* __restrict__ mlp_w1) {
    int idx = blockIdx.x * blockDim.x + threadIdx.x;
    if (idx >= 256*W1ST) return;
    int n = idx >> 6, kp = idx & 63;
    float w0 = 0.f, w1 = 0.f;
    if (n < MLP_H) {
        w0 = mlp_w1[(2*kp)*MLP_H + n];
        w1 = mlp_w1[(2*kp+1)*MLP_H + n];
    }
    __nv_bfloat162 h = __floats2bfloat162_rn(w0, w1);
    __nv_bfloat162 l = __floats2bfloat162_rn(w0 - __bfloat162float(h.x),
                                             w1 - __bfloat162float(h.y));
    g_W1h[idx] = *(uint32_t*)&h;
    g_W1l[idx] = *(uint32_t*)&l;
}

__global__ __launch_bounds__(NTHREADS, 1) void nb101_main(
    const float* __restrict__ adjs,
    const int*   __restrict__ op_inds,
    const float* __restrict__ gcn_b,
    const float* __restrict__ mlp_b1,
    const float* __restrict__ mlp_w2,
    const float* __restrict__ mlp_b2,
    float* __restrict__ out,
    int Btot)
{
    extern __shared__ uint32_t smw[];
    float* smf = (float*)smw;
    int*   RMKp = (int*)(smw + RMK);
    int*   RGIp = (int*)(smw + RGI);
    float* RRDp = (float*)(smw + RRD);

    const uint32_t smem_base = smem_u32(smw);
    const int t  = threadIdx.x;
    const int tx = t & 31;
    const int ty = t >> 5;           // warp id 0..31
    const int gq = tx >> 2;          // mma group id (0..7)
    const int tq = tx & 3;           // thread-in-group
    const int mw = ty >> 2;          // warp m-tile (rows mw*16, 0..7)
    const int nw = ty & 3;           // warp n-tile (cols nw*32)
    const int gbase = blockIdx.x * G;

    // kick off async copy of layer-1 W fragments into smem
    {
        const uint4* srcH = (const uint4*)(g_WPh);
        const uint4* srcL = (const uint4*)(g_WPl);
        uint32_t dH = smem_base + WPH*4;
        uint32_t dL = smem_base + WPL*4;
        for (int i = t; i < 128*PST/4; i += NTHREADS) {
            cpa16(dH + i*16, srcH + i);
            cpa16(dL + i*16, srcL + i);
        }
        asm volatile("cp.async.commit_group;" ::: "memory");
    }

    // stage gate/bias tables; zero AP pad rows (avoid stale NaN patterns)
    for (int i = t; i < N_LAYERS*6*GCN_D; i += NTHREADS) smf[GS + i] = g_gate[i];
    for (int i = t; i < N_LAYERS*GCN_D;   i += NTHREADS) smf[BS + i] = gcn_b[i];
    for (int i = t; i < 16*PST; i += NTHREADS) {
        smw[APH + 112*PST + i] = 0u;
        smw[APL + 112*PST + i] = 0u;
    }

    // per-row metadata (rows 0..111 real, 112..127 pad)
    if (t < 128) {
        int m = 0, gi = 0; float rw = 0.f;
        if (t < G*V) {
            int g = t / V, u = t - g*V;
            int batch = gbase + g;
            if (batch < Btot) {
                const float* arow = adjs + (size_t)batch*(V*V) + u*V;
                m = 1 << u;
                #pragma unroll
                for (int v2 = 0; v2 < V; v2++) if (arow[v2] != 0.f) m |= 1 << v2;
                if (u == 0)        { gi = 0; rw = 0.f; }
                else if (u == V-1) { gi = 5; rw = 1.f/6.f; }
                else {
                    int op = op_inds[(size_t)batch*(V-2) + (u-1)];
                    gi = 1 + op;
                    rw = (op != NONE_OP) ? (1.f/6.f) : 0.f;
                }
            }
        }
        RMKp[t] = m; RGIp[t] = gi; RRDp[t] = rw;
    }
    __syncthreads();

    // ----- layer 0: Y1 = relu(gate0 * (A_aug @ S0) + b0) -> Ysm fp32 -----
    // 2 warps per graph: graph ty>>1, cols (ty&1)*64 + tx*2 (2 cols/thread)
    {
        const int g = ty >> 1, c0 = (ty & 1)*64 + tx*2;
        float2 sv[V];
        #pragma unroll
        for (int v = 0; v < V; v++) sv[v] = __ldg((const float2*)(g_s0 + v*GCN_D + c0));
        const float2 b2v = *(const float2*)(smf + BS + c0);
        #pragma unroll
        for (int u = 0; u < V; u++) {
            int row = g*V + u;
            int m = RMKp[row];
            float s0 = 0.f, s1 = 0.f;
            #pragma unroll
            for (int v = 0; v < V; v++)
                if ((m >> v) & 1) { s0 += sv[v].x; s1 += sv[v].y; }
            const float2 g2 = *(const float2*)(smf + GS + RGIp[row]*GCN_D + c0);
            float y0 = fmaxf(g2.x*s0 + b2v.x, 0.f);
            float y1 = fmaxf(g2.y*s1 + b2v.y, 0.f);
            *(float2*)(smf + YS + row*YST + c0) = make_float2(y0, y1);
        }
    }
    __syncthreads();

    // ldmatrix lane addresses (bytes), computed once
    const int L = tx;
    const int aRowOff = (L & 7) + ((L >> 3) & 1)*8;
    const int aKw     = ((L >> 4) & 1)*4;
    const uint32_t aAddrH = smem_base + (uint32_t)(APH + (mw*16 + aRowOff)*PST + aKw)*4;
    const uint32_t aAddrL = smem_base + (uint32_t)(APL + (mw*16 + aRowOff)*PST + aKw)*4;
    const int bCol = nw*32 + ((L >> 4) & 1)*8 + (L & 7);
    const int bKw  = ((L >> 3) & 1)*4;
    const uint32_t b0H = smem_base + (uint32_t)(WPH + bCol*PST + bKw)*4;
    const uint32_t b0L = smem_base + (uint32_t)(WPL + bCol*PST + bKw)*4;
    const uint32_t b1H = b0H + 16*PST*4;
    const uint32_t b1L = b0L + 16*PST*4;

    // ----- layers 1..4 on tensor cores -----
    for (int li = 1; li < N_LAYERS; li++) {
        if (li > 1) {
            const uint4* srcH = (const uint4*)(g_WPh + (size_t)(li-1)*128*PST);
            const uint4* srcL = (const uint4*)(g_WPl + (size_t)(li-1)*128*PST);
            uint32_t dH = smem_base + WPH*4;
            uint32_t dL = smem_base + WPL*4;
            for (int i = t; i < 128*PST/4; i += NTHREADS) {
                cpa16(dH + i*16, srcH + i);
                cpa16(dL + i*16, srcL + i);
            }
            asm volatile("cp.async.commit_group;" ::: "memory");
        }

        // AY pass: 2 warps/graph, 2 cols/thread -> one hi/lo word per row
        {
            const int g = ty >> 1, c0 = (ty & 1)*64 + tx*2;
            const int wix = c0 >> 1;
            float2 yv[V];
            #pragma unroll
            for (int v = 0; v < V; v++)
                yv[v] = *(const float2*)(smf + YS + (g*V + v)*YST + c0);
            #pragma unroll
            for (int u = 0; u < V; u++) {
                int row = g*V + u;
                int m = RMKp[row];
                float s0 = 0.f, s1 = 0.f;
                #pragma unroll
                for (int v = 0; v < V; v++)
                    if ((m >> v) & 1) { s0 += yv[v].x; s1 += yv[v].y; }
                __nv_bfloat162 h = __floats2bfloat162_rn(s0, s1);
                __nv_bfloat162 l = __floats2bfloat162_rn(s0 - __bfloat162float(h.x),
                                                         s1 - __bfloat162float(h.y));
                smw[APH + row*PST + wix] = *(uint32_t*)&h;
                smw[APL + row*PST + wix] = *(uint32_t*)&l;
            }
        }
        asm volatile("cp.async.wait_group 0;" ::: "memory");
        __syncthreads();

        // GEMM: D(16x32 per warp) = AP @ WP, 3-pass split bf16, LDSM fragment loads
        float d[4][4];
        #pragma unroll
        for (int nt = 0; nt < 4; nt++)
            #pragma unroll
            for (int j = 0; j < 4; j++) d[nt][j] = 0.f;

        #pragma unroll
        for (int kt = 0; kt < 8; kt++) {
            const uint32_t off = kt*32;
            uint32_t ah[4], al[4], bh[8], bl[8];
            ldsm4(ah, aAddrH + off);
            ldsm4(al, aAddrL + off);
            ldsm4(bh,     b0H + off);
            ldsm4(bh + 4, b1H + off);
            ldsm4(bl,     b0L + off);
            ldsm4(bl + 4, b1L + off);
            #pragma unroll
            for (int nt = 0; nt < 4; nt++) {
                mma16816(d[nt], ah, bh + nt*2);
                mma16816(d[nt], al, bh + nt*2);
                mma16816(d[nt], ah, bl + nt*2);
            }
        }

        // pointwise epilogue: y = gate*d + b (+relu), write fp32 Y
        const bool last = (li == N_LAYERS - 1);
        const int R = mw*16 + gq;
        #pragma unroll
        for (int nt = 0; nt < 4; nt++) {
            int C = nw*32 + nt*8 + 2*tq;
            float2 g0 = *(const float2*)(smf + GS + li*6*GCN_D + RGIp[R]*GCN_D + C);
            float2 g1 = *(const float2*)(smf + GS + li*6*GCN_D + RGIp[R+8]*GCN_D + C);
            float2 bb = *(const float2*)(smf + BS + li*GCN_D + C);
            float y0 = g0.x*d[nt][0] + bb.x;
            float y1 = g0.y*d[nt][1] + bb.y;
            float y2 = g1.x*d[nt][2] + bb.x;
            float y3 = g1.y*d[nt][3] + bb.y;
            if (!last) {
                y0 = fmaxf(y0, 0.f); y1 = fmaxf(y1, 0.f);
                y2 = fmaxf(y2, 0.f); y3 = fmaxf(y3, 0.f);
            }
            *(float2*)(smf + YS + R*YST + C)     = make_float2(y0, y1);
            *(float2*)(smf + YS + (R+8)*YST + C) = make_float2(y2, y3);
        }
        __syncthreads();
    }

    // ----- readout: z[g] into AP rows 0..15 (a-frag layout for MLP MMA) -----
    {
        const int g = ty >> 1, c0 = (ty & 1)*64 + tx*2;
        const int wix = c0 >> 1;
        float z0 = 0.f, z1 = 0.f;
        #pragma unroll
        for (int u = 0; u < V; u++) {
            int row = g*V + u;
            float rw = RRDp[row];
            float2 yv = *(const float2*)(smf + YS + row*YST + c0);
            z0 += rw*yv.x; z1 += rw*yv.y;
        }
        __syncthreads();   // all Y/AP consumers done before overwriting AP rows
        __nv_bfloat162 h = __floats2bfloat162_rn(z0, z1);
        __nv_bfloat162 l = __floats2bfloat162_rn(z0 - __bfloat162float(h.x),
                                                 z1 - __bfloat162float(h.y));
        smw[APH + g*PST + wix] = *(uint32_t*)&h;
        smw[APL + g*PST + wix] = *(uint32_t*)&l;
    }
    __syncthreads();

    // ----- MLP layer 1 via MMA: h(16 x 256pad) = z @ w1; fold relu+w2 reduction -----
    // 32 warps x one 8-col n-tile each
    {
        const uint32_t zAddrH = smem_base + (uint32_t)(APH + aRowOff*PST + aKw)*4;
        const uint32_t zAddrL = smem_base + (uint32_t)(APL + aRowOff*PST + aKw)*4;
        float d[4] = {0.f, 0.f, 0.f, 0.f};
        #pragma unroll
        for (int kt = 0; kt < 8; kt++) {
            const int kb = kt*8 + tq;
            uint32_t ah[4], al[4], bh[2], bl[2];
            ldsm4(ah, zAddrH + kt*32);
            ldsm4(al, zAddrL + kt*32);
            int rn = (ty*8 + gq)*W1ST + kb;
            bh[0] = __ldg(g_W1h + rn); bh[1] = __ldg(g_W1h + rn + 4);
            bl[0] = __ldg(g_W1l + rn); bl[1] = __ldg(g_W1l + rn + 4);
            mma16816(d, ah, bh);
            mma16816(d, al, bh);
            mma16816(d, ah, bl);
        }

        // bias + relu + w2 scale; partials for graphs gq (rows 0-7) and gq+8
        float p0 = 0.f, p1 = 0.f;
        #pragma unroll
        for (int e = 0; e < 2; e++) {
            int j = ty*8 + 2*tq + e;
            if (j < MLP_H) {
                float b1v = __ldg(mlp_b1 + j);
                float w2v = __ldg(mlp_w2 + j);
                p0 += fmaxf(d[e]     + b1v, 0.f) * w2v;
                p1 += fmaxf(d[2 + e] + b1v, 0.f) * w2v;
            }
        }
        p0 += __shfl_down_sync(0xffffffffu, p0, 1);
        p0 += __shfl_down_sync(0xffffffffu, p0, 2);
        p1 += __shfl_down_sync(0xffffffffu, p1, 1);
        p1 += __shfl_down_sync(0xffffffffu, p1, 2);
        if (tq == 0) {
            smf[PART + gq*32 + ty]       = p0;
            smf[PART + (gq + 8)*32 + ty] = p1;
        }
    }
    __syncthreads();

    // final reduce: warp g (<16) reduces its 32 partials
    if (ty < G) {
        float p = smf[PART + ty*32 + tx];
        #pragma unroll
        for (int o = 16; o > 0; o >>= 1) p += __shfl_down_sync(0xffffffffu, p, o);
        if (tx == 0 && (gbase + ty) < Btot) out[gbase + ty] = p + __ldg(mlp_b2);
    }
}

extern "C" void kernel_launch(void* const* d_in, const int* in_sizes, int n_in,
                              void* d_out, int out_size)
{
    const float* adjs           = (const float*)d_in[0];
    const int*   op_inds        = (const int*)  d_in[1];
    const float* input_node_emb = (const float*)d_in[2];
    const float* other_node_emb = (const float*)d_in[3];
    const float* input_op_emb   = (const float*)d_in[4];
    const float* op_emb_table   = (const float*)d_in[5];
    const float* output_op_emb  = (const float*)d_in[6];
    const float* xh_w           = (const float*)d_in[7];
    const float* xh_b           = (const float*)d_in[8];
    const float* gcn0_w         = (const float*)d_in[9];
    const float* gcn_w          = (const float*)d_in[10];
    const float* attn_w         = (const float*)d_in[11];
    const float* attn_b         = (const float*)d_in[12];
    const float* gcn_b          = (const float*)d_in[13];
    const float* mlp_w1         = (const float*)d_in[14];
    const float* mlp_b1         = (const float*)d_in[15];
    const float* mlp_w2         = (const float*)d_in[16];
    const float* mlp_b2         = (const float*)d_in[17];
    float* out = (float*)d_out;

    int Btot = in_sizes[0] / (V*V);

    precompute_kernel<<<1, 256>>>(input_node_emb, other_node_emb, input_op_emb,
                                  op_emb_table, output_op_emb, xh_w, xh_b,
                                  gcn0_w, attn_w, attn_b);
    prep_w_kernel<<<((N_LAYERS-1)*GCN_D*64 + 255)/256, 256>>>(gcn_w);
    prep_w1_kernel<<<(256*W1ST + 255)/256, 256>>>(mlp_w1);

    size_t smem = SMEM_WORDS * sizeof(uint32_t);
    cudaFuncSetAttribute(nb101_main, cudaFuncAttributeMaxDynamicSharedMemorySize, (int)smem);
    int grid = (Btot + G - 1) / G;
    nb101_main<<<grid, NTHREADS, smem>>>(adjs, op_inds, gcn_b,
                                         mlp_b1, mlp_w2, mlp_b2, out, Btot);
}

// round 14
// speedup vs baseline: 2.6078x; 1.2740x over previous
#include <cuda_runtime.h>
#include <cuda_fp16.h>
#include <math.h>
#include <stdint.h>

#define V 7
#define NODE_D 48
#define OP_D 48
#define HID 96
#define GCN_D 128
#define N_LAYERS 5
#define MLP_H 200
#define NONE_OP 3

#define G 16             // graphs per CTA -> 112 real rows of a 128-row GEMM
#define NTHREADS 1024    // 32 warps: 8 m-tiles x 4 n-tiles of 16x32
#define YST 132          // fp32 Y stride (words)
#define PST 68           // packed fp16-pair stride (u32 words per row)
#define W1ST 64          // packed w1 fragment stride

// ---- shared memory word (u32) offsets ----
#define APH 0                      // A hi pairs: 128*68
#define APL (APH + 128*PST)        // 8704
#define WPH (APL + 128*PST)        // 17408 : W fp16 pairs (single precision level)
#define YS  (WPH + 128*PST)        // 26112 : fp32 Y 128*132 = 16896
#define GS  (YS + 128*YST)         // 43008 : gates 5*6*128 = 3840
#define BS  (GS + N_LAYERS*6*GCN_D)// 46848 : biases 5*128 = 640
#define RMK (BS + N_LAYERS*GCN_D)  // 47488
#define RGI (RMK + 128)            // 47616
#define RRD (RGI + 128)            // 47744
#define PART (RRD + 128)           // 47872 : MLP partials 16 graphs x 32 warps
#define SMEM_WORDS (PART + 512)    // 48384 words = 193536 B

typedef unsigned long long ull;

// Precomputed, batch-independent tables
__device__ float g_s0[V*GCN_D];
__device__ float g_gate[N_LAYERS*6*GCN_D];
__device__ uint32_t g_WPk[(N_LAYERS-1)*128*PST];  // W fp16, fragment layout [n][kpair] (PST-padded)
__device__ uint32_t g_W1k[256*W1ST];              // mlp_w1 fp16 fragments [n][kpair]

__device__ __forceinline__ void mma16816(float* d, const uint32_t* a, const uint32_t* b) {
    asm volatile("mma.sync.aligned.m16n8k16.row.col.f32.f16.f16.f32 "
        "{%0,%1,%2,%3}, {%4,%5,%6,%7}, {%8,%9}, {%0,%1,%2,%3};"
        : "+f"(d[0]), "+f"(d[1]), "+f"(d[2]), "+f"(d[3])
        : "r"(a[0]), "r"(a[1]), "r"(a[2]), "r"(a[3]), "r"(b[0]), "r"(b[1]));
}
__device__ __forceinline__ void ldsm4(uint32_t* r, uint32_t addr) {
    asm volatile("ldmatrix.sync.aligned.m8n8.x4.shared.b16 {%0,%1,%2,%3}, [%4];"
        : "=r"(r[0]), "=r"(r[1]), "=r"(r[2]), "=r"(r[3]) : "r"(addr));
}
__device__ __forceinline__ uint32_t smem_u32(const void* p) {
    uint32_t a;
    asm("{ .reg .u64 t; cvta.to.shared.u64 t, %1; cvt.u32.u64 %0, t; }" : "=r"(a) : "l"(p));
    return a;
}
__device__ __forceinline__ void cpa16(uint32_t dst, const void* src) {
    asm volatile("cp.async.cg.shared.global [%0], [%1], 16;" :: "r"(dst), "l"(src));
}
// split two floats into fp16 hi pair + fp16 lo pair
__device__ __forceinline__ void split2(float x, float y, uint32_t& h, uint32_t& l) {
    __half2 hh = __floats2half2_rn(x, y);
    __half2 ll = __floats2half2_rn(x - __half2float(__low2half(hh)),
                                   y - __half2float(__high2half(hh)));
    h = *(uint32_t*)&hh;
    l = *(uint32_t*)&ll;
}

__global__ void precompute_kernel(
    const float* __restrict__ input_node_emb,
    const float* __restrict__ other_node_emb,
    const float* __restrict__ input_op_emb,
    const float* __restrict__ op_emb_table,
    const float* __restrict__ output_op_emb,
    const float* __restrict__ xh_w,
    const float* __restrict__ xh_b,
    const float* __restrict__ gcn0_w,
    const float* __restrict__ attn_w,
    const float* __restrict__ attn_b)
{
    __shared__ float y0[2][HID];
    int t = threadIdx.x;
    if (t < 2*HID) {
        int r = t / HID, c = t % HID;
        const float* e = (r == 0) ? input_node_emb : other_node_emb;
        float acc = xh_b[c];
        for (int d = 0; d < NODE_D; d++) acc += e[d] * xh_w[d*HID + c];
        y0[r][c] = acc;
    }
    __syncthreads();
    for (int idx = t; idx < V*GCN_D; idx += blockDim.x) {
        int v = idx / GCN_D, n = idx % GCN_D;
        const float* yr = y0[(v == 0) ? 0 : 1];
        float acc = 0.f;
        for (int d = 0; d < HID; d++) acc += yr[d] * gcn0_w[d*GCN_D + n];
        g_s0[idx] = acc;
    }
    for (int idx = t; idx < N_LAYERS*6*GCN_D; idx += blockDim.x) {
        int i = idx / (6*GCN_D);
        int r = idx % (6*GCN_D);
        int gi = r / GCN_D, n = r % GCN_D;
        const float* e = (gi == 0) ? input_op_emb
                       : (gi <= 4 ? op_emb_table + (gi-1)*OP_D : output_op_emb);
        float acc = attn_b[i*GCN_D + n];
        for (int d = 0; d < OP_D; d++) acc += e[d] * attn_w[(i*OP_D + d)*GCN_D + n];
        g_gate[idx] = 1.f / (1.f + expf(-acc));
    }
}

// Pack gcn_w into mma B-fragment layout: [n][kpair], fp16, PST-padded rows.
__global__ void prep_w_kernel(const float* __restrict__ gcn_w) {
    int idx = blockIdx.x * blockDim.x + threadIdx.x;
    if (idx >= (N_LAYERS-1)*GCN_D*64) return;
    int li = idx >> 13;
    int r  = idx & 8191;
    int n  = r >> 6, kp = r & 63;
    const float* wl = gcn_w + (size_t)li*GCN_D*GCN_D;
    __half2 h = __floats2half2_rn(wl[(2*kp)*GCN_D + n], wl[(2*kp+1)*GCN_D + n]);
    g_WPk[li*128*PST + n*PST + kp] = *(uint32_t*)&h;
}

// Pack mlp_w1 into fragment layout [n(256, zero-pad >=200)][kpair], fp16.
__global__ void prep_w1_kernel(const float* __restrict__ mlp_w1) {
    int idx = blockIdx.x * blockDim.x + threadIdx.x;
    if (idx >= 256*W1ST) return;
    int n = idx >> 6, kp = idx & 63;
    float w0 = 0.f, w1 = 0.f;
    if (n < MLP_H) {
        w0 = mlp_w1[(2*kp)*MLP_H + n];
        w1 = mlp_w1[(2*kp+1)*MLP_H + n];
    }
    __half2 h = __floats2half2_rn(w0, w1);
    g_W1k[idx] = *(uint32_t*)&h;
}

__global__ __launch_bounds__(NTHREADS, 1) void nb101_main(
    const float* __restrict__ adjs,
    const int*   __restrict__ op_inds,
    const float* __restrict__ gcn_b,
    const float* __restrict__ mlp_b1,
    const float* __restrict__ mlp_w2,
    const float* __restrict__ mlp_b2,
    float* __restrict__ out,
    int Btot)
{
    extern __shared__ uint32_t smw[];
    float* smf = (float*)smw;
    int*   RMKp = (int*)(smw + RMK);
    int*   RGIp = (int*)(smw + RGI);
    float* RRDp = (float*)(smw + RRD);

    const uint32_t smem_base = smem_u32(smw);
    const int t  = threadIdx.x;
    const int tx = t & 31;
    const int ty = t >> 5;           // warp id 0..31
    const int gq = tx >> 2;          // mma group id (0..7)
    const int tq = tx & 3;           // thread-in-group
    const int mw = ty >> 2;          // warp m-tile (rows mw*16, 0..7)
    const int nw = ty & 3;           // warp n-tile (cols nw*32)
    const int gbase = blockIdx.x * G;

    // kick off async copy of layer-1 W fragments into smem
    {
        const uint4* srcW = (const uint4*)(g_WPk);
        uint32_t dW = smem_base + WPH*4;
        for (int i = t; i < 128*PST/4; i += NTHREADS)
            cpa16(dW + i*16, srcW + i);
        asm volatile("cp.async.commit_group;" ::: "memory");
    }

    // stage gate/bias tables; zero AP pad rows
    for (int i = t; i < N_LAYERS*6*GCN_D; i += NTHREADS) smf[GS + i] = g_gate[i];
    for (int i = t; i < N_LAYERS*GCN_D;   i += NTHREADS) smf[BS + i] = gcn_b[i];
    for (int i = t; i < 16*PST; i += NTHREADS) {
        smw[APH + 112*PST + i] = 0u;
        smw[APL + 112*PST + i] = 0u;
    }

    // per-row metadata (rows 0..111 real, 112..127 pad)
    if (t < 128) {
        int m = 0, gi = 0; float rw = 0.f;
        if (t < G*V) {
            int g = t / V, u = t - g*V;
            int batch = gbase + g;
            if (batch < Btot) {
                const float* arow = adjs + (size_t)batch*(V*V) + u*V;
                m = 1 << u;
                #pragma unroll
                for (int v2 = 0; v2 < V; v2++) if (arow[v2] != 0.f) m |= 1 << v2;
                if (u == 0)        { gi = 0; rw = 0.f; }
                else if (u == V-1) { gi = 5; rw = 1.f/6.f; }
                else {
                    int op = op_inds[(size_t)batch*(V-2) + (u-1)];
                    gi = 1 + op;
                    rw = (op != NONE_OP) ? (1.f/6.f) : 0.f;
                }
            }
        }
        RMKp[t] = m; RGIp[t] = gi; RRDp[t] = rw;
    }
    __syncthreads();

    // ----- layer 0: Y1 = relu(gate0 * (A_aug @ S0) + b0) -> Ysm fp32 -----
    {
        const int g = ty >> 1, c0 = (ty & 1)*64 + tx*2;
        float2 sv[V];
        #pragma unroll
        for (int v = 0; v < V; v++) sv[v] = __ldg((const float2*)(g_s0 + v*GCN_D + c0));
        const float2 b2v = *(const float2*)(smf + BS + c0);
        #pragma unroll
        for (int u = 0; u < V; u++) {
            int row = g*V + u;
            int m = RMKp[row];
            float s0 = 0.f, s1 = 0.f;
            #pragma unroll
            for (int v = 0; v < V; v++)
                if ((m >> v) & 1) { s0 += sv[v].x; s1 += sv[v].y; }
            const float2 g2 = *(const float2*)(smf + GS + RGIp[row]*GCN_D + c0);
            float y0 = fmaxf(g2.x*s0 + b2v.x, 0.f);
            float y1 = fmaxf(g2.y*s1 + b2v.y, 0.f);
            *(float2*)(smf + YS + row*YST + c0) = make_float2(y0, y1);
        }
    }
    __syncthreads();

    // ldmatrix lane addresses (bytes), computed once
    const int L = tx;
    const int aRowOff = (L & 7) + ((L >> 3) & 1)*8;
    const int aKw     = ((L >> 4) & 1)*4;
    const uint32_t aAddrH = smem_base + (uint32_t)(APH + (mw*16 + aRowOff)*PST + aKw)*4;
    const uint32_t aAddrL = smem_base + (uint32_t)(APL + (mw*16 + aRowOff)*PST + aKw)*4;
    const int bCol = nw*32 + ((L >> 4) & 1)*8 + (L & 7);
    const int bKw  = ((L >> 3) & 1)*4;
    const uint32_t b0W = smem_base + (uint32_t)(WPH + bCol*PST + bKw)*4;
    const uint32_t b1W = b0W + 16*PST*4;

    // ----- layers 1..4 on tensor cores (2-pass split-fp16 A, fp16 W) -----
    for (int li = 1; li < N_LAYERS; li++) {
        if (li > 1) {
            const uint4* srcW = (const uint4*)(g_WPk + (size_t)(li-1)*128*PST);
            uint32_t dW = smem_base + WPH*4;
            for (int i = t; i < 128*PST/4; i += NTHREADS)
                cpa16(dW + i*16, srcW + i);
            asm volatile("cp.async.commit_group;" ::: "memory");
        }

        // AY pass: 2 warps/graph, 2 cols/thread -> one hi/lo word per row
        {
            const int g = ty >> 1, c0 = (ty & 1)*64 + tx*2;
            const int wix = c0 >> 1;
            float2 yv[V];
            #pragma unroll
            for (int v = 0; v < V; v++)
                yv[v] = *(const float2*)(smf + YS + (g*V + v)*YST + c0);
            #pragma unroll
            for (int u = 0; u < V; u++) {
                int row = g*V + u;
                int m = RMKp[row];
                float s0 = 0.f, s1 = 0.f;
                #pragma unroll
                for (int v = 0; v < V; v++)
                    if ((m >> v) & 1) { s0 += yv[v].x; s1 += yv[v].y; }
                uint32_t h, l;
                split2(s0, s1, h, l);
                smw[APH + row*PST + wix] = h;
                smw[APL + row*PST + wix] = l;
            }
        }
        asm volatile("cp.async.wait_group 0;" ::: "memory");
        __syncthreads();

        // GEMM: D(16x32 per warp) = AP @ WP, 2-pass, LDSM fragment loads
        float d[4][4];
        #pragma unroll
        for (int nt = 0; nt < 4; nt++)
            #pragma unroll
            for (int j = 0; j < 4; j++) d[nt][j] = 0.f;

        #pragma unroll
        for (int kt = 0; kt < 8; kt++) {
            const uint32_t off = kt*32;
            uint32_t ah[4], al[4], bw[8];
            ldsm4(ah, aAddrH + off);
            ldsm4(al, aAddrL + off);
            ldsm4(bw,     b0W + off);
            ldsm4(bw + 4, b1W + off);
            #pragma unroll
            for (int nt = 0; nt < 4; nt++) {
                mma16816(d[nt], ah, bw + nt*2);
                mma16816(d[nt], al, bw + nt*2);
            }
        }

        // pointwise epilogue: y = gate*d + b (+relu), write fp32 Y
        const bool last = (li == N_LAYERS - 1);
        const int R = mw*16 + gq;
        #pragma unroll
        for (int nt = 0; nt < 4; nt++) {
            int C = nw*32 + nt*8 + 2*tq;
            float2 g0 = *(const float2*)(smf + GS + li*6*GCN_D + RGIp[R]*GCN_D + C);
            float2 g1 = *(const float2*)(smf + GS + li*6*GCN_D + RGIp[R+8]*GCN_D + C);
            float2 bb = *(const float2*)(smf + BS + li*GCN_D + C);
            float y0 = g0.x*d[nt][0] + bb.x;
            float y1 = g0.y*d[nt][1] + bb.y;
            float y2 = g1.x*d[nt][2] + bb.x;
            float y3 = g1.y*d[nt][3] + bb.y;
            if (!last) {
                y0 = fmaxf(y0, 0.f); y1 = fmaxf(y1, 0.f);
                y2 = fmaxf(y2, 0.f); y3 = fmaxf(y3, 0.f);
            }
            *(float2*)(smf + YS + R*YST + C)     = make_float2(y0, y1);
            *(float2*)(smf + YS + (R+8)*YST + C) = make_float2(y2, y3);
        }
        __syncthreads();
    }

    // ----- readout: z[g] into AP rows 0..15 (a-frag layout for MLP MMA) -----
    {
        const int g = ty >> 1, c0 = (ty & 1)*64 + tx*2;
        const int wix = c0 >> 1;
        float z0 = 0.f, z1 = 0.f;
        #pragma unroll
        for (int u = 0; u < V; u++) {
            int row = g*V + u;
            float rw = RRDp[row];
            float2 yv = *(const float2*)(smf + YS + row*YST + c0);
            z0 += rw*yv.x; z1 += rw*yv.y;
        }
        __syncthreads();   // all AP consumers done before overwriting AP rows
        uint32_t h, l;
        split2(z0, z1, h, l);
        smw[APH + g*PST + wix] = h;
        smw[APL + g*PST + wix] = l;
    }
    __syncthreads();

    // ----- MLP layer 1 via MMA: h(16 x 256pad) = z @ w1; fold relu+w2 reduction -----
    {
        const uint32_t zAddrH = smem_base + (uint32_t)(APH + aRowOff*PST + aKw)*4;
        const uint32_t zAddrL = smem_base + (uint32_t)(APL + aRowOff*PST + aKw)*4;
        float d[4] = {0.f, 0.f, 0.f, 0.f};
        #pragma unroll
        for (int kt = 0; kt < 8; kt++) {
            const int kb = kt*8 + tq;
            uint32_t ah[4], al[4], bw[2];
            ldsm4(ah, zAddrH + kt*32);
            ldsm4(al, zAddrL + kt*32);
            int rn = (ty*8 + gq)*W1ST + kb;
            bw[0] = __ldg(g_W1k + rn); bw[1] = __ldg(g_W1k + rn + 4);
            mma16816(d, ah, bw);
            mma16816(d, al, bw);
        }

        // bias + relu + w2 scale; partials for graphs gq (rows 0-7) and gq+8
        float p0 = 0.f, p1 = 0.f;
        #pragma unroll
        for (int e = 0; e < 2; e++) {
            int j = ty*8 + 2*tq + e;
            if (j < MLP_H) {
                float b1v = __ldg(mlp_b1 + j);
                float w2v = __ldg(mlp_w2 + j);
                p0 += fmaxf(d[e]     + b1v, 0.f) * w2v;
                p1 += fmaxf(d[2 + e] + b1v, 0.f) * w2v;
            }
        }
        p0 += __shfl_down_sync(0xffffffffu, p0, 1);
        p0 += __shfl_down_sync(0xffffffffu, p0, 2);
        p1 += __shfl_down_sync(0xffffffffu, p1, 1);
        p1 += __shfl_down_sync(0xffffffffu, p1, 2);
        if (tq == 0) {
            smf[PART + gq*32 + ty]       = p0;
            smf[PART + (gq + 8)*32 + ty] = p1;
        }
    }
    __syncthreads();

    // final reduce: warp g (<16) reduces its 32 partials
    if (ty < G) {
        float p = smf[PART + ty*32 + tx];
        #pragma unroll
        for (int o = 16; o > 0; o >>= 1) p += __shfl_down_sync(0xffffffffu, p, o);
        if (tx == 0 && (gbase + ty) < Btot) out[gbase + ty] = p + __ldg(mlp_b2);
    }
}

extern "C" void kernel_launch(void* const* d_in, const int* in_sizes, int n_in,
                              void* d_out, int out_size)
{
    const float* adjs           = (const float*)d_in[0];
    const int*   op_inds        = (const int*)  d_in[1];
    const float* input_node_emb = (const float*)d_in[2];
    const float* other_node_emb = (const float*)d_in[3];
    const float* input_op_emb   = (const float*)d_in[4];
    const float* op_emb_table   = (const float*)d_in[5];
    const float* output_op_emb  = (const float*)d_in[6];
    const float* xh_w           = (const float*)d_in[7];
    const float* xh_b           = (const float*)d_in[8];
    const float* gcn0_w         = (const float*)d_in[9];
    const float* gcn_w          = (const float*)d_in[10];
    const float* attn_w         = (const float*)d_in[11];
    const float* attn_b         = (const float*)d_in[12];
    const float* gcn_b          = (const float*)d_in[13];
    const float* mlp_w1         = (const float*)d_in[14];
    const float* mlp_b1         = (const float*)d_in[15];
    const float* mlp_w2         = (const float*)d_in[16];
    const float* mlp_b2         = (const float*)d_in[17];
    float* out = (float*)d_out;

    int Btot = in_sizes[0] / (V*V);

    precompute_kernel<<<1, 256>>>(input_node_emb, other_node_emb, input_op_emb,
                                  op_emb_table, output_op_emb, xh_w, xh_b,
                                  gcn0_w, attn_w, attn_b);
    prep_w_kernel<<<((N_LAYERS-1)*GCN_D*64 + 255)/256, 256>>>(gcn_w);
    prep_w1_kernel<<<(256*W1ST + 255)/256, 256>>>(mlp_w1);

    size_t smem = SMEM_WORDS * sizeof(uint32_t);
    cudaFuncSetAttribute(nb101_main, cudaFuncAttributeMaxDynamicSharedMemorySize, (int)smem);
    int grid = (Btot + G - 1) / G;
    nb101_main<<<grid, NTHREADS, smem>>>(adjs, op_inds, gcn_b,
                                         mlp_b1, mlp_w2, mlp_b2, out, Btot);
}

// round 15
// speedup vs baseline: 2.6428x; 1.0134x over previous
#include <cuda_runtime.h>
#include <cuda_fp16.h>
#include <math.h>
#include <stdint.h>

#define V 7
#define NODE_D 48
#define OP_D 48
#define HID 96
#define GCN_D 128
#define N_LAYERS 5
#define MLP_H 200
#define NONE_OP 3

#define G 16             // graphs per CTA -> 112 real rows of a 128-row GEMM
#define NTHREADS 1024    // 32 warps: 8 m-tiles x 4 n-tiles of 16x32
#define YST 132          // fp32 Y stride (words)
#define PST 68           // packed fp16-pair stride (u32 words per row)
#define GST 132          // padded gate-table stride (kills bank conflicts)
#define W1ST 64          // packed w1 fragment stride

// ---- shared memory word (u32) offsets ----
#define APH 0                      // A hi pairs: 128*68
#define APL (APH + 128*PST)        // 8704
#define WPH (APL + 128*PST)        // 17408 : W fp16 pairs
#define YS  (WPH + 128*PST)        // 26112 : fp32 Y 128*132 = 16896
#define GS  (YS + 128*YST)         // 43008 : gates 5*6 rows x GST = 3960
#define BS  (GS + N_LAYERS*6*GST)  // 46968 : biases 5*128 = 640
#define RMK (BS + N_LAYERS*GCN_D)  // 47608
#define RGI (RMK + 128)            // 47736
#define RRD (RGI + 128)            // 47864
#define PART (RRD + 128)           // 47992 : MLP partials 16 graphs x 32 warps
#define SMEM_WORDS (PART + 512)    // 48504 words = 194016 B

typedef unsigned long long ull;

// Precomputed, batch-independent tables
__device__ float g_s0[V*GCN_D];
__device__ float g_gate[N_LAYERS*6*GCN_D];
__device__ uint32_t g_WPk[(N_LAYERS-1)*128*PST];  // W fp16, fragment layout [n][kpair] (PST-padded)
__device__ uint32_t g_W1k[256*W1ST];              // mlp_w1 fp16 fragments [n][kpair]

__device__ __forceinline__ void mma16816(float* d, const uint32_t* a, const uint32_t* b) {
    asm volatile("mma.sync.aligned.m16n8k16.row.col.f32.f16.f16.f32 "
        "{%0,%1,%2,%3}, {%4,%5,%6,%7}, {%8,%9}, {%0,%1,%2,%3};"
        : "+f"(d[0]), "+f"(d[1]), "+f"(d[2]), "+f"(d[3])
        : "r"(a[0]), "r"(a[1]), "r"(a[2]), "r"(a[3]), "r"(b[0]), "r"(b[1]));
}
__device__ __forceinline__ void ldsm4(uint32_t* r, uint32_t addr) {
    asm volatile("ldmatrix.sync.aligned.m8n8.x4.shared.b16 {%0,%1,%2,%3}, [%4];"
        : "=r"(r[0]), "=r"(r[1]), "=r"(r[2]), "=r"(r[3]) : "r"(addr));
}
__device__ __forceinline__ uint32_t smem_u32(const void* p) {
    uint32_t a;
    asm("{ .reg .u64 t; cvta.to.shared.u64 t, %1; cvt.u32.u64 %0, t; }" : "=r"(a) : "l"(p));
    return a;
}
__device__ __forceinline__ void cpa16(uint32_t dst, const void* src) {
    asm volatile("cp.async.cg.shared.global [%0], [%1], 16;" :: "r"(dst), "l"(src));
}
__device__ __forceinline__ void add2(ull& d, ull a, ull b) {
    asm("add.rn.f32x2 %0, %1, %2;" : "=l"(d) : "l"(a), "l"(b));
}
__device__ __forceinline__ void unpack2(ull v, float& x, float& y) {
    asm("mov.b64 {%0, %1}, %2;" : "=f"(x), "=f"(y) : "l"(v));
}
// split two floats into fp16 hi pair + fp16 lo pair
__device__ __forceinline__ void split2(float x, float y, uint32_t& h, uint32_t& l) {
    __half2 hh = __floats2half2_rn(x, y);
    __half2 ll = __floats2half2_rn(x - __half2float(__low2half(hh)),
                                   y - __half2float(__high2half(hh)));
    h = *(uint32_t*)&hh;
    l = *(uint32_t*)&ll;
}

__global__ void precompute_kernel(
    const float* __restrict__ input_node_emb,
    const float* __restrict__ other_node_emb,
    const float* __restrict__ input_op_emb,
    const float* __restrict__ op_emb_table,
    const float* __restrict__ output_op_emb,
    const float* __restrict__ xh_w,
    const float* __restrict__ xh_b,
    const float* __restrict__ gcn0_w,
    const float* __restrict__ attn_w,
    const float* __restrict__ attn_b)
{
    __shared__ float y0[2][HID];
    int t = threadIdx.x;
    if (t < 2*HID) {
        int r = t / HID, c = t % HID;
        const float* e = (r == 0) ? input_node_emb : other_node_emb;
        float acc = xh_b[c];
        for (int d = 0; d < NODE_D; d++) acc += e[d] * xh_w[d*HID + c];
        y0[r][c] = acc;
    }
    __syncthreads();
    for (int idx = t; idx < V*GCN_D; idx += blockDim.x) {
        int v = idx / GCN_D, n = idx % GCN_D;
        const float* yr = y0[(v == 0) ? 0 : 1];
        float acc = 0.f;
        for (int d = 0; d < HID; d++) acc += yr[d] * gcn0_w[d*GCN_D + n];
        g_s0[idx] = acc;
    }
    for (int idx = t; idx < N_LAYERS*6*GCN_D; idx += blockDim.x) {
        int i = idx / (6*GCN_D);
        int r = idx % (6*GCN_D);
        int gi = r / GCN_D, n = r % GCN_D;
        const float* e = (gi == 0) ? input_op_emb
                       : (gi <= 4 ? op_emb_table + (gi-1)*OP_D : output_op_emb);
        float acc = attn_b[i*GCN_D + n];
        for (int d = 0; d < OP_D; d++) acc += e[d] * attn_w[(i*OP_D + d)*GCN_D + n];
        g_gate[idx] = 1.f / (1.f + expf(-acc));
    }
}

// Pack gcn_w into mma B-fragment layout: [n][kpair], fp16, PST-padded rows.
__global__ void prep_w_kernel(const float* __restrict__ gcn_w) {
    int idx = blockIdx.x * blockDim.x + threadIdx.x;
    if (idx >= (N_LAYERS-1)*GCN_D*64) return;
    int li = idx >> 13;
    int r  = idx & 8191;
    int n  = r >> 6, kp = r & 63;
    const float* wl = gcn_w + (size_t)li*GCN_D*GCN_D;
    __half2 h = __floats2half2_rn(wl[(2*kp)*GCN_D + n], wl[(2*kp+1)*GCN_D + n]);
    g_WPk[li*128*PST + n*PST + kp] = *(uint32_t*)&h;
}

// Pack mlp_w1 into fragment layout [n(256, zero-pad >=200)][kpair], fp16.
__global__ void prep_w1_kernel(const float* __restrict__ mlp_w1) {
    int idx = blockIdx.x * blockDim.x + threadIdx.x;
    if (idx >= 256*W1ST) return;
    int n = idx >> 6, kp = idx & 63;
    float w0 = 0.f, w1 = 0.f;
    if (n < MLP_H) {
        w0 = mlp_w1[(2*kp)*MLP_H + n];
        w1 = mlp_w1[(2*kp+1)*MLP_H + n];
    }
    __half2 h = __floats2half2_rn(w0, w1);
    g_W1k[idx] = *(uint32_t*)&h;
}

__global__ __launch_bounds__(NTHREADS, 1) void nb101_main(
    const float* __restrict__ adjs,
    const int*   __restrict__ op_inds,
    const float* __restrict__ gcn_b,
    const float* __restrict__ mlp_b1,
    const float* __restrict__ mlp_w2,
    const float* __restrict__ mlp_b2,
    float* __restrict__ out,
    int Btot)
{
    extern __shared__ uint32_t smw[];
    float* smf = (float*)smw;
    int*   RMKp = (int*)(smw + RMK);
    int*   RGIp = (int*)(smw + RGI);
    float* RRDp = (float*)(smw + RRD);

    const uint32_t smem_base = smem_u32(smw);
    const int t  = threadIdx.x;
    const int tx = t & 31;
    const int ty = t >> 5;           // warp id 0..31
    const int gq = tx >> 2;          // mma group id (0..7)
    const int tq = tx & 3;           // thread-in-group
    const int mw = ty >> 2;          // warp m-tile (rows mw*16, 0..7)
    const int nw = ty & 3;           // warp n-tile (cols nw*32)
    const int gbase = blockIdx.x * G;

    // kick off async copy of layer-1 W fragments into smem
    {
        const uint4* srcW = (const uint4*)(g_WPk);
        uint32_t dW = smem_base + WPH*4;
        for (int i = t; i < 128*PST/4; i += NTHREADS)
            cpa16(dW + i*16, srcW + i);
        asm volatile("cp.async.commit_group;" ::: "memory");
    }

    // stage gate (padded GST rows) / bias tables; zero AP pad rows
    for (int i = t; i < N_LAYERS*6*GCN_D; i += NTHREADS)
        smf[GS + (i >> 7)*GST + (i & 127)] = g_gate[i];
    for (int i = t; i < N_LAYERS*GCN_D;   i += NTHREADS) smf[BS + i] = gcn_b[i];
    for (int i = t; i < 16*PST; i += NTHREADS) {
        smw[APH + 112*PST + i] = 0u;
        smw[APL + 112*PST + i] = 0u;
    }

    // per-row metadata (rows 0..111 real, 112..127 pad)
    if (t < 128) {
        int m = 0, gi = 0; float rw = 0.f;
        if (t < G*V) {
            int g = t / V, u = t - g*V;
            int batch = gbase + g;
            if (batch < Btot) {
                const float* arow = adjs + (size_t)batch*(V*V) + u*V;
                m = 1 << u;
                #pragma unroll
                for (int v2 = 0; v2 < V; v2++) if (arow[v2] != 0.f) m |= 1 << v2;
                if (u == 0)        { gi = 0; rw = 0.f; }
                else if (u == V-1) { gi = 5; rw = 1.f/6.f; }
                else {
                    int op = op_inds[(size_t)batch*(V-2) + (u-1)];
                    gi = 1 + op;
                    rw = (op != NONE_OP) ? (1.f/6.f) : 0.f;
                }
            }
        }
        RMKp[t] = m; RGIp[t] = gi; RRDp[t] = rw;
    }
    __syncthreads();

    // ----- layer 0: Y1 = relu(gate0 * (A_aug @ S0) + b0) -> Ysm fp32 -----
    {
        const int g = ty >> 1, c0 = (ty & 1)*64 + tx*2;
        float2 sv[V];
        #pragma unroll
        for (int v = 0; v < V; v++) sv[v] = __ldg((const float2*)(g_s0 + v*GCN_D + c0));
        const float2 b2v = *(const float2*)(smf + BS + c0);
        #pragma unroll
        for (int u = 0; u < V; u++) {
            int row = g*V + u;
            int m = RMKp[row];
            float s0 = 0.f, s1 = 0.f;
            #pragma unroll
            for (int v = 0; v < V; v++)
                if ((m >> v) & 1) { s0 += sv[v].x; s1 += sv[v].y; }
            const float2 g2 = *(const float2*)(smf + GS + RGIp[row]*GST + c0);
            float y0 = fmaxf(g2.x*s0 + b2v.x, 0.f);
            float y1 = fmaxf(g2.y*s1 + b2v.y, 0.f);
            *(float2*)(smf + YS + row*YST + c0) = make_float2(y0, y1);
        }
    }
    __syncthreads();

    // ldmatrix lane addresses (bytes), computed once
    const int L = tx;
    const int aRowOff = (L & 7) + ((L >> 3) & 1)*8;
    const int aKw     = ((L >> 4) & 1)*4;
    const uint32_t aAddrH = smem_base + (uint32_t)(APH + (mw*16 + aRowOff)*PST + aKw)*4;
    const uint32_t aAddrL = smem_base + (uint32_t)(APL + (mw*16 + aRowOff)*PST + aKw)*4;
    const int bCol = nw*32 + ((L >> 4) & 1)*8 + (L & 7);
    const int bKw  = ((L >> 3) & 1)*4;
    const uint32_t b0W = smem_base + (uint32_t)(WPH + bCol*PST + bKw)*4;
    const uint32_t b1W = b0W + 16*PST*4;

    // ----- layers 1..4 on tensor cores (2-pass split-fp16 A, fp16 W) -----
    for (int li = 1; li < N_LAYERS; li++) {
        if (li > 1) {
            const uint4* srcW = (const uint4*)(g_WPk + (size_t)(li-1)*128*PST);
            uint32_t dW = smem_base + WPH*4;
            for (int i = t; i < 128*PST/4; i += NTHREADS)
                cpa16(dW + i*16, srcW + i);
            asm volatile("cp.async.commit_group;" ::: "memory");
        }

        // AY pass: 2 warps/graph, 2 cols/thread; packed f32x2 masked sums
        {
            const int g = ty >> 1, c0 = (ty & 1)*64 + tx*2;
            const int wix = c0 >> 1;
            ull yv[V];
            #pragma unroll
            for (int v = 0; v < V; v++)
                yv[v] = *(const ull*)(smf + YS + (g*V + v)*YST + c0);
            #pragma unroll
            for (int u = 0; u < V; u++) {
                int row = g*V + u;
                int m = RMKp[row];
                ull s = 0ull;
                #pragma unroll
                for (int v = 0; v < V; v++)
                    if ((m >> v) & 1) add2(s, s, yv[v]);
                float s0, s1;
                unpack2(s, s0, s1);
                uint32_t h, l;
                split2(s0, s1, h, l);
                smw[APH + row*PST + wix] = h;
                smw[APL + row*PST + wix] = l;
            }
        }
        asm volatile("cp.async.wait_group 0;" ::: "memory");
        __syncthreads();

        // GEMM: D(16x32 per warp) = AP @ WP, 2-pass, LDSM fragment loads
        float d[4][4];
        #pragma unroll
        for (int nt = 0; nt < 4; nt++)
            #pragma unroll
            for (int j = 0; j < 4; j++) d[nt][j] = 0.f;

        #pragma unroll
        for (int kt = 0; kt < 8; kt++) {
            const uint32_t off = kt*32;
            uint32_t ah[4], al[4], bw[8];
            ldsm4(ah, aAddrH + off);
            ldsm4(al, aAddrL + off);
            ldsm4(bw,     b0W + off);
            ldsm4(bw + 4, b1W + off);
            #pragma unroll
            for (int nt = 0; nt < 4; nt++) {
                mma16816(d[nt], ah, bw + nt*2);
                mma16816(d[nt], al, bw + nt*2);
            }
        }

        // pointwise epilogue: y = gate*d + b (+relu), write fp32 Y
        const bool last = (li == N_LAYERS - 1);
        const int R = mw*16 + gq;
        #pragma unroll
        for (int nt = 0; nt < 4; nt++) {
            int C = nw*32 + nt*8 + 2*tq;
            float2 g0 = *(const float2*)(smf + GS + (li*6 + RGIp[R])*GST + C);
            float2 g1 = *(const float2*)(smf + GS + (li*6 + RGIp[R+8])*GST + C);
            float2 bb = *(const float2*)(smf + BS + li*GCN_D + C);
            float y0 = g0.x*d[nt][0] + bb.x;
            float y1 = g0.y*d[nt][1] + bb.y;
            float y2 = g1.x*d[nt][2] + bb.x;
            float y3 = g1.y*d[nt][3] + bb.y;
            if (!last) {
                y0 = fmaxf(y0, 0.f); y1 = fmaxf(y1, 0.f);
                y2 = fmaxf(y2, 0.f); y3 = fmaxf(y3, 0.f);
            }
            *(float2*)(smf + YS + R*YST + C)     = make_float2(y0, y1);
            *(float2*)(smf + YS + (R+8)*YST + C) = make_float2(y2, y3);
        }
        __syncthreads();
    }

    // ----- readout: z[g] into AP rows 0..15 (a-frag layout for MLP MMA) -----
    // AP's last readers (layer-4 GEMM) finished before the loop-end barrier.
    {
        const int g = ty >> 1, c0 = (ty & 1)*64 + tx*2;
        const int wix = c0 >> 1;
        float z0 = 0.f, z1 = 0.f;
        #pragma unroll
        for (int u = 0; u < V; u++) {
            int row = g*V + u;
            float rw = RRDp[row];
            float2 yv = *(const float2*)(smf + YS + row*YST + c0);
            z0 += rw*yv.x; z1 += rw*yv.y;
        }
        uint32_t h, l;
        split2(z0, z1, h, l);
        smw[APH + g*PST + wix] = h;
        smw[APL + g*PST + wix] = l;
    }
    __syncthreads();

    // ----- MLP layer 1 via MMA: h(16 x 256pad) = z @ w1; fold relu+w2 reduction -----
    {
        const uint32_t zAddrH = smem_base + (uint32_t)(APH + aRowOff*PST + aKw)*4;
        const uint32_t zAddrL = smem_base + (uint32_t)(APL + aRowOff*PST + aKw)*4;
        float d[4] = {0.f, 0.f, 0.f, 0.f};
        #pragma unroll
        for (int kt = 0; kt < 8; kt++) {
            const int kb = kt*8 + tq;
            uint32_t ah[4], al[4], bw[2];
            ldsm4(ah, zAddrH + kt*32);
            ldsm4(al, zAddrL + kt*32);
            int rn = (ty*8 + gq)*W1ST + kb;
            bw[0] = __ldg(g_W1k + rn); bw[1] = __ldg(g_W1k + rn + 4);
            mma16816(d, ah, bw);
            mma16816(d, al, bw);
        }

        // bias + relu + w2 scale; partials for graphs gq (rows 0-7) and gq+8
        float p0 = 0.f, p1 = 0.f;
        #pragma unroll
        for (int e = 0; e < 2; e++) {
            int j = ty*8 + 2*tq + e;
            if (j < MLP_H) {
                float b1v = __ldg(mlp_b1 + j);
                float w2v = __ldg(mlp_w2 + j);
                p0 += fmaxf(d[e]     + b1v, 0.f) * w2v;
                p1 += fmaxf(d[2 + e] + b1v, 0.f) * w2v;
            }
        }
        p0 += __shfl_down_sync(0xffffffffu, p0, 1);
        p0 += __shfl_down_sync(0xffffffffu, p0, 2);
        p1 += __shfl_down_sync(0xffffffffu, p1, 1);
        p1 += __shfl_down_sync(0xffffffffu, p1, 2);
        if (tq == 0) {
            smf[PART + gq*32 + ty]       = p0;
            smf[PART + (gq + 8)*32 + ty] = p1;
        }
    }
    __syncthreads();

    // final reduce: warp g (<16) reduces its 32 partials
    if (ty < G) {
        float p = smf[PART + ty*32 + tx];
        #pragma unroll
        for (int o = 16; o > 0; o >>= 1) p += __shfl_down_sync(0xffffffffu, p, o);
        if (tx == 0 && (gbase + ty) < Btot) out[gbase + ty] = p + __ldg(mlp_b2);
    }
}

extern "C" void kernel_launch(void* const* d_in, const int* in_sizes, int n_in,
                              void* d_out, int out_size)
{
    const float* adjs           = (const float*)d_in[0];
    const int*   op_inds        = (const int*)  d_in[1];
    const float* input_node_emb = (const float*)d_in[2];
    const float* other_node_emb = (const float*)d_in[3];
    const float* input_op_emb   = (const float*)d_in[4];
    const float* op_emb_table   = (const float*)d_in[5];
    const float* output_op_emb  = (const float*)d_in[6];
    const float* xh_w           = (const float*)d_in[7];
    const float* xh_b           = (const float*)d_in[8];
    const float* gcn0_w         = (const float*)d_in[9];
    const float* gcn_w          = (const float*)d_in[10];
    const float* attn_w         = (const float*)d_in[11];
    const float* attn_b         = (const float*)d_in[12];
    const float* gcn_b           = (const float*)d_in[13];
    const float* mlp_w1         = (const float*)d_in[14];
    const float* mlp_b1         = (const float*)d_in[15];
    const float* mlp_w2         = (const float*)d_in[16];
    const float* mlp_b2         = (const float*)d_in[17];
    float* out = (float*)d_out;

    int Btot = in_sizes[0] / (V*V);

    precompute_kernel<<<1, 256>>>(input_node_emb, other_node_emb, input_op_emb,
                                  op_emb_table, output_op_emb, xh_w, xh_b,
                                  gcn0_w, attn_w, attn_b);
    prep_w_kernel<<<((N_LAYERS-1)*GCN_D*64 + 255)/256, 256>>>(gcn_w);
    prep_w1_kernel<<<(256*W1ST + 255)/256, 256>>>(mlp_w1);

    size_t smem = SMEM_WORDS * sizeof(uint32_t);
    cudaFuncSetAttribute(nb101_main, cudaFuncAttributeMaxDynamicSharedMemorySize, (int)smem);
    int grid = (Btot + G - 1) / G;
    nb101_main<<<grid, NTHREADS, smem>>>(adjs, op_inds, gcn_b,
                                         mlp_b1, mlp_w2, mlp_b2, out, Btot);
}

// round 16
// speedup vs baseline: 2.6875x; 1.0169x over previous
#include <cuda_runtime.h>
#include <cuda_fp16.h>
#include <math.h>
#include <stdint.h>

#define V 7
#define NODE_D 48
#define OP_D 48
#define HID 96
#define GCN_D 128
#define N_LAYERS 5
#define MLP_H 200
#define NONE_OP 3

#define G 8              // graphs per CTA, 8-row aligned -> 64-row GEMM
#define NTHREADS 512     // 16 warps: 4 m-tiles x 4 n-tiles of 16x32
#define NROWS 64
#define PST 68           // packed fp16-pair stride (u32 words per row)
#define GST 132          // padded gate-table stride
#define W1ST 64          // packed w1 fragment stride

// ---- shared memory word (u32) offsets ----
#define XPH 0                      // shared Y/AP hi pairs: 64*68 = 4352
#define XPL (XPH + NROWS*PST)      // 4352
#define WPS (XPL + NROWS*PST)      // 8704 : W fp16 fragments 128*68
#define GSo (WPS + 128*PST)        // 17408 : gates layers1-4, 24 rows x GST = 3168
#define BSo (GSo + 24*GST)         // 20576 : biases 5*128 = 640
#define RMK (BSo + N_LAYERS*GCN_D) // 21216
#define RGI (RMK + NROWS)          // 21280
#define RRD (RGI + NROWS)          // 21344
#define PARTo (RRD + NROWS)        // 21408 : MLP partials 8 graphs x 16 warps
#define SMEM_WORDS (PARTo + 128)   // 21536 words = 86144 B  (2 CTAs/SM)

// Precomputed, batch-independent tables
__device__ float g_s0[V*GCN_D];
__device__ float g_gate[N_LAYERS*6*GCN_D];
__device__ uint32_t g_WPk[(N_LAYERS-1)*128*PST];  // W fp16, fragment layout [n][kpair] (PST-padded)
__device__ uint32_t g_W1k[256*W1ST];              // mlp_w1 fp16 fragments [n][kpair]

__device__ __forceinline__ void mma16816(float* d, const uint32_t* a, const uint32_t* b) {
    asm volatile("mma.sync.aligned.m16n8k16.row.col.f32.f16.f16.f32 "
        "{%0,%1,%2,%3}, {%4,%5,%6,%7}, {%8,%9}, {%0,%1,%2,%3};"
        : "+f"(d[0]), "+f"(d[1]), "+f"(d[2]), "+f"(d[3])
        : "r"(a[0]), "r"(a[1]), "r"(a[2]), "r"(a[3]), "r"(b[0]), "r"(b[1]));
}
__device__ __forceinline__ void ldsm4(uint32_t* r, uint32_t addr) {
    asm volatile("ldmatrix.sync.aligned.m8n8.x4.shared.b16 {%0,%1,%2,%3}, [%4];"
        : "=r"(r[0]), "=r"(r[1]), "=r"(r[2]), "=r"(r[3]) : "r"(addr));
}
__device__ __forceinline__ uint32_t smem_u32(const void* p) {
    uint32_t a;
    asm("{ .reg .u64 t; cvta.to.shared.u64 t, %1; cvt.u32.u64 %0, t; }" : "=r"(a) : "l"(p));
    return a;
}
__device__ __forceinline__ void cpa16(uint32_t dst, const void* src) {
    asm volatile("cp.async.cg.shared.global [%0], [%1], 16;" :: "r"(dst), "l"(src));
}
// split two floats into fp16 hi pair + fp16 lo pair
__device__ __forceinline__ void split2(float x, float y, uint32_t& h, uint32_t& l) {
    __half2 hh = __floats2half2_rn(x, y);
    __half2 ll = __floats2half2_rn(x - __half2float(__low2half(hh)),
                                   y - __half2float(__high2half(hh)));
    h = *(uint32_t*)&hh;
    l = *(uint32_t*)&ll;
}
__device__ __forceinline__ float2 join2(uint32_t h, uint32_t l) {
    float2 a = __half22float2(*(__half2*)&h);
    float2 b = __half22float2(*(__half2*)&l);
    return make_float2(a.x + b.x, a.y + b.y);
}
#define BAR_MW(mw) asm volatile("bar.sync %0, 128;" :: "r"(1 + (mw)) : "memory")

__global__ void precompute_kernel(
    const float* __restrict__ input_node_emb,
    const float* __restrict__ other_node_emb,
    const float* __restrict__ input_op_emb,
    const float* __restrict__ op_emb_table,
    const float* __restrict__ output_op_emb,
    const float* __restrict__ xh_w,
    const float* __restrict__ xh_b,
    const float* __restrict__ gcn0_w,
    const float* __restrict__ attn_w,
    const float* __restrict__ attn_b)
{
    __shared__ float y0[2][HID];
    int t = threadIdx.x;
    if (t < 2*HID) {
        int r = t / HID, c = t % HID;
        const float* e = (r == 0) ? input_node_emb : other_node_emb;
        float acc = xh_b[c];
        for (int d = 0; d < NODE_D; d++) acc += e[d] * xh_w[d*HID + c];
        y0[r][c] = acc;
    }
    __syncthreads();
    for (int idx = t; idx < V*GCN_D; idx += blockDim.x) {
        int v = idx / GCN_D, n = idx % GCN_D;
        const float* yr = y0[(v == 0) ? 0 : 1];
        float acc = 0.f;
        for (int d = 0; d < HID; d++) acc += yr[d] * gcn0_w[d*GCN_D + n];
        g_s0[idx] = acc;
    }
    for (int idx = t; idx < N_LAYERS*6*GCN_D; idx += blockDim.x) {
        int i = idx / (6*GCN_D);
        int r = idx % (6*GCN_D);
        int gi = r / GCN_D, n = r % GCN_D;
        const float* e = (gi == 0) ? input_op_emb
                       : (gi <= 4 ? op_emb_table + (gi-1)*OP_D : output_op_emb);
        float acc = attn_b[i*GCN_D + n];
        for (int d = 0; d < OP_D; d++) acc += e[d] * attn_w[(i*OP_D + d)*GCN_D + n];
        g_gate[idx] = 1.f / (1.f + expf(-acc));
    }
}

// Pack gcn_w into mma B-fragment layout: [n][kpair], fp16, PST-padded rows.
__global__ void prep_w_kernel(const float* __restrict__ gcn_w) {
    int idx = blockIdx.x * blockDim.x + threadIdx.x;
    if (idx >= (N_LAYERS-1)*GCN_D*64) return;
    int li = idx >> 13;
    int r  = idx & 8191;
    int n  = r >> 6, kp = r & 63;
    const float* wl = gcn_w + (size_t)li*GCN_D*GCN_D;
    __half2 h = __floats2half2_rn(wl[(2*kp)*GCN_D + n], wl[(2*kp+1)*GCN_D + n]);
    g_WPk[li*128*PST + n*PST + kp] = *(uint32_t*)&h;
}

// Pack mlp_w1 into fragment layout [n(256, zero-pad >=200)][kpair], fp16.
__global__ void prep_w1_kernel(const float* __restrict__ mlp_w1) {
    int idx = blockIdx.x * blockDim.x + threadIdx.x;
    if (idx >= 256*W1ST) return;
    int n = idx >> 6, kp = idx & 63;
    float w0 = 0.f, w1 = 0.f;
    if (n < MLP_H) {
        w0 = mlp_w1[(2*kp)*MLP_H + n];
        w1 = mlp_w1[(2*kp+1)*MLP_H + n];
    }
    __half2 h = __floats2half2_rn(w0, w1);
    g_W1k[idx] = *(uint32_t*)&h;
}

__global__ __launch_bounds__(NTHREADS, 2) void nb101_main(
    const float* __restrict__ adjs,
    const int*   __restrict__ op_inds,
    const float* __restrict__ gcn_b,
    const float* __restrict__ mlp_b1,
    const float* __restrict__ mlp_w2,
    const float* __restrict__ mlp_b2,
    float* __restrict__ out,
    int Btot)
{
    extern __shared__ uint32_t smw[];
    float* smf = (float*)smw;
    int*   RMKp = (int*)(smw + RMK);
    int*   RGIp = (int*)(smw + RGI);
    float* RRDp = (float*)(smw + RRD);

    const uint32_t smem_base = smem_u32(smw);
    const int t  = threadIdx.x;
    const int tx = t & 31;
    const int ty = t >> 5;           // warp id 0..15
    const int gq = tx >> 2;          // mma group id (0..7)
    const int tq = tx & 3;           // thread-in-group
    const int mw = ty >> 2;          // warp m-tile (rows mw*16, 0..3)
    const int nw = ty & 3;           // warp n-tile (cols nw*32)
    const int gbase = blockIdx.x * G;

    // kick off async copy of layer-1 W fragments into smem
    {
        const uint4* srcW = (const uint4*)(g_WPk);
        uint32_t dW = smem_base + WPS*4;
        for (int i = t; i < 128*PST/4; i += NTHREADS)
            cpa16(dW + i*16, srcW + i);
        asm volatile("cp.async.commit_group;" ::: "memory");
    }

    // stage gate rows (layers 1..4, padded GST) and biases (all layers)
    for (int i = t; i < 24*GCN_D; i += NTHREADS)
        smf[GSo + (i >> 7)*GST + (i & 127)] = g_gate[6*GCN_D + i];
    for (int i = t; i < N_LAYERS*GCN_D; i += NTHREADS) smf[BSo + i] = gcn_b[i];

    // per-row metadata; rows = g*8+u, u=7 is pad
    if (t < NROWS) {
        int g = t >> 3, u = t & 7;
        int m = 0, gi = 0; float rw = 0.f;
        int batch = gbase + g;
        if (u < 7 && batch < Btot) {
            const float* arow = adjs + (size_t)batch*(V*V) + u*V;
            m = 1 << u;
            #pragma unroll
            for (int v2 = 0; v2 < V; v2++) if (arow[v2] != 0.f) m |= 1 << v2;
            if (u == 0)        { gi = 0; rw = 0.f; }
            else if (u == V-1) { gi = 5; rw = 1.f/6.f; }
            else {
                int op = op_inds[(size_t)batch*(V-2) + (u-1)];
                gi = 1 + op;
                rw = (op != NONE_OP) ? (1.f/6.f) : 0.f;
            }
        }
        RMKp[t] = m; RGIp[t] = gi; RRDp[t] = rw;
    }
    __syncthreads();

    // ----- layer 0: Y1 = relu(gate0*(A_aug@S0)+b0) -> XP fp16 pairs -----
    // warp ty handles graph ty>>1, col half ty&1 (2 cols per thread)
    {
        const int g = ty >> 1, c0 = (ty & 1)*64 + tx*2;
        const int wix = c0 >> 1;
        float2 sv[V];
        #pragma unroll
        for (int v = 0; v < V; v++) sv[v] = __ldg((const float2*)(g_s0 + v*GCN_D + c0));
        const float2 b2v = *(const float2*)(smf + BSo + c0);
        #pragma unroll
        for (int u = 0; u < V; u++) {
            int row = g*8 + u;
            int m = RMKp[row];
            float s0 = 0.f, s1 = 0.f;
            #pragma unroll
            for (int v = 0; v < V; v++)
                if ((m >> v) & 1) { s0 += sv[v].x; s1 += sv[v].y; }
            const float2 g2 = __ldg((const float2*)(g_gate + RGIp[row]*GCN_D + c0));
            float y0v = fmaxf(g2.x*s0 + b2v.x, 0.f);
            float y1v = fmaxf(g2.y*s1 + b2v.y, 0.f);
            uint32_t h, l;
            split2(y0v, y1v, h, l);
            smw[XPH + row*PST + wix] = h;
            smw[XPL + row*PST + wix] = l;
        }
        // zero the pad row
        smw[XPH + (g*8 + 7)*PST + wix] = 0u;
        smw[XPL + (g*8 + 7)*PST + wix] = 0u;
    }
    // layer-0 writers of graphs 2mw,2mw+1 are exactly warps 4mw..4mw+3
    BAR_MW(mw);

    // ldmatrix lane addresses (bytes), computed once
    const int L = tx;
    const int aRowOff = (L & 7) + ((L >> 3) & 1)*8;
    const int aKw     = ((L >> 4) & 1)*4;
    const uint32_t aAddrH = smem_base + (uint32_t)(XPH + (mw*16 + aRowOff)*PST + aKw)*4;
    const uint32_t aAddrL = smem_base + (uint32_t)(XPL + (mw*16 + aRowOff)*PST + aKw)*4;
    const int bCol = nw*32 + ((L >> 4) & 1)*8 + (L & 7);
    const int bKw  = ((L >> 3) & 1)*4;
    const uint32_t b0W = smem_base + (uint32_t)(WPS + bCol*PST + bKw)*4;
    const uint32_t b1W = b0W + 16*PST*4;

    // AY assignment: mw-group handles its own graphs 2mw, 2mw+1
    const int ayG   = 2*mw + (nw & 1);
    const int ayWix = (nw >> 1)*32 + tx;

    // ----- layers 1..4 on tensor cores (2-pass split-fp16 A, fp16 W) -----
    for (int li = 1; li < N_LAYERS; li++) {
        // AY: read Y pairs (hi+lo), masked sums, write AP pairs into SAME buffer
        {
            float2 yv[V];
            #pragma unroll
            for (int v = 0; v < V; v++) {
                int row = ayG*8 + v;
                yv[v] = join2(smw[XPH + row*PST + ayWix], smw[XPL + row*PST + ayWix]);
            }
            #pragma unroll
            for (int u = 0; u < V; u++) {
                int row = ayG*8 + u;
                int m = RMKp[row];
                float s0 = 0.f, s1 = 0.f;
                #pragma unroll
                for (int v = 0; v < V; v++)
                    if ((m >> v) & 1) { s0 += yv[v].x; s1 += yv[v].y; }
                uint32_t h, l;
                split2(s0, s1, h, l);
                smw[XPH + row*PST + ayWix] = h;
                smw[XPL + row*PST + ayWix] = l;
            }
            // keep pad row zero (epilogue overwrites it each layer)
            smw[XPH + (ayG*8 + 7)*PST + ayWix] = 0u;
            smw[XPL + (ayG*8 + 7)*PST + ayWix] = 0u;
        }
        asm volatile("cp.async.wait_group 0;" ::: "memory");
        __syncthreads();   // B1: W_li staged+visible; own AP ready (program order)

        // GEMM: D(16x32 per warp) = AP @ W, 2-pass, LDSM fragment loads
        float d[4][4];
        #pragma unroll
        for (int nt = 0; nt < 4; nt++)
            #pragma unroll
            for (int j = 0; j < 4; j++) d[nt][j] = 0.f;

        #pragma unroll
        for (int kt = 0; kt < 8; kt++) {
            const uint32_t off = kt*32;
            uint32_t ah[4], al[4], bw[8];
            ldsm4(ah, aAddrH + off);
            ldsm4(al, aAddrL + off);
            ldsm4(bw,     b0W + off);
            ldsm4(bw + 4, b1W + off);
            #pragma unroll
            for (int nt = 0; nt < 4; nt++) {
                mma16816(d[nt], ah, bw + nt*2);
                mma16816(d[nt], al, bw + nt*2);
            }
        }
        __syncthreads();   // B2: all W_li + AP reads done

        // prefetch next layer's W (overlaps epilogue + next AY)
        if (li < N_LAYERS - 1) {
            const uint4* srcW = (const uint4*)(g_WPk + (size_t)li*128*PST);
            uint32_t dW = smem_base + WPS*4;
            for (int i = t; i < 128*PST/4; i += NTHREADS)
                cpa16(dW + i*16, srcW + i);
            asm volatile("cp.async.commit_group;" ::: "memory");
        }

        // epilogue: y = gate*d + b (+relu), write fp16 pairs into XP
        const bool last = (li == N_LAYERS - 1);
        const int R = mw*16 + gq;
        #pragma unroll
        for (int nt = 0; nt < 4; nt++) {
            int C = nw*32 + nt*8 + 2*tq;
            float2 g0 = *(const float2*)(smf + GSo + ((li-1)*6 + RGIp[R])*GST + C);
            float2 g1 = *(const float2*)(smf + GSo + ((li-1)*6 + RGIp[R+8])*GST + C);
            float2 bb = *(const float2*)(smf + BSo + li*GCN_D + C);
            float y0 = g0.x*d[nt][0] + bb.x;
            float y1 = g0.y*d[nt][1] + bb.y;
            float y2 = g1.x*d[nt][2] + bb.x;
            float y3 = g1.y*d[nt][3] + bb.y;
            if (!last) {
                y0 = fmaxf(y0, 0.f); y1 = fmaxf(y1, 0.f);
                y2 = fmaxf(y2, 0.f); y3 = fmaxf(y3, 0.f);
            }
            uint32_t h, l;
            split2(y0, y1, h, l);
            smw[XPH + R*PST + (C >> 1)] = h;
            smw[XPL + R*PST + (C >> 1)] = l;
            split2(y2, y3, h, l);
            smw[XPH + (R+8)*PST + (C >> 1)] = h;
            smw[XPL + (R+8)*PST + (C >> 1)] = l;
        }
        BAR_MW(mw);        // local: own group's Y ready for its AY / readout
    }

    // ----- readout: z[g] = sum_u rw*Y[g*8+u] (regs), then store to XP rows 0..15 -----
    float z0 = 0.f, z1 = 0.f;
    {
        #pragma unroll
        for (int u = 0; u < V; u++) {
            int row = ayG*8 + u;
            float rw = RRDp[row];
            float2 yv = join2(smw[XPH + row*PST + ayWix], smw[XPL + row*PST + ayWix]);
            z0 += rw*yv.x; z1 += rw*yv.y;
        }
    }
    __syncthreads();       // all Y reads complete before z overwrites rows 0..15
    {
        uint32_t h, l;
        split2(z0, z1, h, l);
        smw[XPH + ayG*PST + ayWix] = h;
        smw[XPL + ayG*PST + ayWix] = l;
        // zero rows 8..15 (pad rows of the MLP m16 tile)
        if (t < 512) {
            int r = 8 + (t >> 6), w = t & 63;
            smw[XPH + r*PST + w] = 0u;
            smw[XPL + r*PST + w] = 0u;
        }
    }
    __syncthreads();

    // ----- MLP layer 1 via MMA: h(16 x 256pad) = z @ w1; fold relu+w2 reduction -----
    {
        const uint32_t zAddrH = smem_base + (uint32_t)(XPH + aRowOff*PST + aKw)*4;
        const uint32_t zAddrL = smem_base + (uint32_t)(XPL + aRowOff*PST + aKw)*4;
        float d[2][4];
        #pragma unroll
        for (int nt = 0; nt < 2; nt++)
            #pragma unroll
            for (int j = 0; j < 4; j++) d[nt][j] = 0.f;
        #pragma unroll
        for (int kt = 0; kt < 8; kt++) {
            const int kb = kt*8 + tq;
            uint32_t ah[4], al[4], bw[2];
            ldsm4(ah, zAddrH + kt*32);
            ldsm4(al, zAddrL + kt*32);
            #pragma unroll
            for (int nt = 0; nt < 2; nt++) {
                int rn = (ty*16 + nt*8 + gq)*W1ST + kb;
                bw[0] = __ldg(g_W1k + rn); bw[1] = __ldg(g_W1k + rn + 4);
                mma16816(d[nt], ah, bw);
                mma16816(d[nt], al, bw);
            }
        }

        // bias + relu + w2 scale; rows gq<8 = graph gq (rows 8..15 are zero pad, discard)
        float p0 = 0.f;
        #pragma unroll
        for (int nt = 0; nt < 2; nt++) {
            #pragma unroll
            for (int e = 0; e < 2; e++) {
                int j = ty*16 + nt*8 + 2*tq + e;
                if (j < MLP_H) {
                    float b1v = __ldg(mlp_b1 + j);
                    float w2v = __ldg(mlp_w2 + j);
                    p0 += fmaxf(d[nt][e] + b1v, 0.f) * w2v;
                }
            }
        }
        p0 += __shfl_down_sync(0xffffffffu, p0, 1);
        p0 += __shfl_down_sync(0xffffffffu, p0, 2);
        if (tq == 0) smf[PARTo + gq*16 + ty] = p0;
    }
    __syncthreads();

    // final reduce: warp g (<8) reduces its 16 partials
    if (ty < G) {
        float p = (tx < 16) ? smf[PARTo + ty*16 + tx] : 0.f;
        #pragma unroll
        for (int o = 8; o > 0; o >>= 1) p += __shfl_down_sync(0xffffffffu, p, o);
        if (tx == 0 && (gbase + ty) < Btot) out[gbase + ty] = p + __ldg(mlp_b2);
    }
}

extern "C" void kernel_launch(void* const* d_in, const int* in_sizes, int n_in,
                              void* d_out, int out_size)
{
    const float* adjs           = (const float*)d_in[0];
    const int*   op_inds        = (const int*)  d_in[1];
    const float* input_node_emb = (const float*)d_in[2];
    const float* other_node_emb = (const float*)d_in[3];
    const float* input_op_emb   = (const float*)d_in[4];
    const float* op_emb_table   = (const float*)d_in[5];
    const float* output_op_emb  = (const float*)d_in[6];
    const float* xh_w           = (const float*)d_in[7];
    const float* xh_b           = (const float*)d_in[8];
    const float* gcn0_w         = (const float*)d_in[9];
    const float* gcn_w          = (const float*)d_in[10];
    const float* attn_w         = (const float*)d_in[11];
    const float* attn_b         = (const float*)d_in[12];
    const float* gcn_b          = (const float*)d_in[13];
    const float* mlp_w1         = (const float*)d_in[14];
    const float* mlp_b1         = (const float*)d_in[15];
    const float* mlp_w2         = (const float*)d_in[16];
    const float* mlp_b2         = (const float*)d_in[17];
    float* out = (float*)d_out;

    int Btot = in_sizes[0] / (V*V);

    precompute_kernel<<<1, 256>>>(input_node_emb, other_node_emb, input_op_emb,
                                  op_emb_table, output_op_emb, xh_w, xh_b,
                                  gcn0_w, attn_w, attn_b);
    prep_w_kernel<<<((N_LAYERS-1)*GCN_D*64 + 255)/256, 256>>>(gcn_w);
    prep_w1_kernel<<<(256*W1ST + 255)/256, 256>>>(mlp_w1);

    size_t smem = SMEM_WORDS * sizeof(uint32_t);
    cudaFuncSetAttribute(nb101_main, cudaFuncAttributeMaxDynamicSharedMemorySize, (int)smem);
    int grid = (Btot + G - 1) / G;
    nb101_main<<<grid, NTHREADS, smem>>>(adjs, op_inds, gcn_b,
                                         mlp_b1, mlp_w2, mlp_b2, out, Btot);
}

// round 17
// speedup vs baseline: 2.8483x; 1.0598x over previous
#include <cuda_runtime.h>
#include <cuda_fp16.h>
#include <math.h>
#include <stdint.h>

#define V 7
#define NODE_D 48
#define OP_D 48
#define HID 96
#define GCN_D 128
#define N_LAYERS 5
#define MLP_H 200
#define NONE_OP 3

#define G 8              // graphs per CTA, 8-row aligned -> 64-row GEMM
#define NTHREADS 256     // 8 warps: 2 m-tiles x 4 n-tiles of 32x32
#define NROWS 64
#define PST 68           // packed fp16-pair stride (u32 words per row)
#define GST 132          // padded gate-table stride
#define W1ST 64          // packed w1 fragment stride

// ---- shared memory word (u32) offsets ----
#define XPH 0                      // shared Y/AP hi pairs: 64*68 = 4352
#define XPL (XPH + NROWS*PST)      // 4352
#define WPS (XPL + NROWS*PST)      // 8704 : W fp16 fragments 128*68
#define GSo (WPS + 128*PST)        // 17408 : gates layers1-4, 24 rows x GST = 3168
#define BSo (GSo + 24*GST)         // 20576 : biases 5*128 = 640
#define RMK (BSo + N_LAYERS*GCN_D) // 21216
#define RGI (RMK + NROWS)          // 21280
#define RRD (RGI + NROWS)          // 21344
#define PARTo (RRD + NROWS)        // 21408 : MLP partials 8 graphs x 8 warps
#define SMEM_WORDS (PARTo + 64)    // 21472 words = 85888 B  (2 CTAs/SM)

// Precomputed, batch-independent tables
__device__ float g_s0[V*GCN_D];
__device__ float g_gate[N_LAYERS*6*GCN_D];
__device__ uint32_t g_WPk[(N_LAYERS-1)*128*PST];  // W fp16, fragment layout [n][kpair] (PST-padded)
__device__ uint32_t g_W1k[256*W1ST];              // mlp_w1 fp16 fragments [n][kpair]

__device__ __forceinline__ void mma16816(float* d, const uint32_t* a, const uint32_t* b) {
    asm volatile("mma.sync.aligned.m16n8k16.row.col.f32.f16.f16.f32 "
        "{%0,%1,%2,%3}, {%4,%5,%6,%7}, {%8,%9}, {%0,%1,%2,%3};"
        : "+f"(d[0]), "+f"(d[1]), "+f"(d[2]), "+f"(d[3])
        : "r"(a[0]), "r"(a[1]), "r"(a[2]), "r"(a[3]), "r"(b[0]), "r"(b[1]));
}
__device__ __forceinline__ void ldsm4(uint32_t* r, uint32_t addr) {
    asm volatile("ldmatrix.sync.aligned.m8n8.x4.shared.b16 {%0,%1,%2,%3}, [%4];"
        : "=r"(r[0]), "=r"(r[1]), "=r"(r[2]), "=r"(r[3]) : "r"(addr));
}
__device__ __forceinline__ uint32_t smem_u32(const void* p) {
    uint32_t a;
    asm("{ .reg .u64 t; cvta.to.shared.u64 t, %1; cvt.u32.u64 %0, t; }" : "=r"(a) : "l"(p));
    return a;
}
__device__ __forceinline__ void cpa16(uint32_t dst, const void* src) {
    asm volatile("cp.async.cg.shared.global [%0], [%1], 16;" :: "r"(dst), "l"(src));
}
// split two floats into fp16 hi pair + fp16 lo pair
__device__ __forceinline__ void split2(float x, float y, uint32_t& h, uint32_t& l) {
    __half2 hh = __floats2half2_rn(x, y);
    __half2 ll = __floats2half2_rn(x - __half2float(__low2half(hh)),
                                   y - __half2float(__high2half(hh)));
    h = *(uint32_t*)&hh;
    l = *(uint32_t*)&ll;
}
__device__ __forceinline__ float2 join2(uint32_t h, uint32_t l) {
    float2 a = __half22float2(*(__half2*)&h);
    float2 b = __half22float2(*(__half2*)&l);
    return make_float2(a.x + b.x, a.y + b.y);
}
#define BAR_MW(mw) asm volatile("bar.sync %0, 128;" :: "r"(1 + (mw)) : "memory")

__global__ void precompute_kernel(
    const float* __restrict__ input_node_emb,
    const float* __restrict__ other_node_emb,
    const float* __restrict__ input_op_emb,
    const float* __restrict__ op_emb_table,
    const float* __restrict__ output_op_emb,
    const float* __restrict__ xh_w,
    const float* __restrict__ xh_b,
    const float* __restrict__ gcn0_w,
    const float* __restrict__ attn_w,
    const float* __restrict__ attn_b)
{
    __shared__ float y0[2][HID];
    int t = threadIdx.x;
    if (t < 2*HID) {
        int r = t / HID, c = t % HID;
        const float* e = (r == 0) ? input_node_emb : other_node_emb;
        float acc = xh_b[c];
        for (int d = 0; d < NODE_D; d++) acc += e[d] * xh_w[d*HID + c];
        y0[r][c] = acc;
    }
    __syncthreads();
    for (int idx = t; idx < V*GCN_D; idx += blockDim.x) {
        int v = idx / GCN_D, n = idx % GCN_D;
        const float* yr = y0[(v == 0) ? 0 : 1];
        float acc = 0.f;
        for (int d = 0; d < HID; d++) acc += yr[d] * gcn0_w[d*GCN_D + n];
        g_s0[idx] = acc;
    }
    for (int idx = t; idx < N_LAYERS*6*GCN_D; idx += blockDim.x) {
        int i = idx / (6*GCN_D);
        int r = idx % (6*GCN_D);
        int gi = r / GCN_D, n = r % GCN_D;
        const float* e = (gi == 0) ? input_op_emb
                       : (gi <= 4 ? op_emb_table + (gi-1)*OP_D : output_op_emb);
        float acc = attn_b[i*GCN_D + n];
        for (int d = 0; d < OP_D; d++) acc += e[d] * attn_w[(i*OP_D + d)*GCN_D + n];
        g_gate[idx] = 1.f / (1.f + expf(-acc));
    }
}

// Pack gcn_w into mma B-fragment layout: [n][kpair], fp16, PST-padded rows.
__global__ void prep_w_kernel(const float* __restrict__ gcn_w) {
    int idx = blockIdx.x * blockDim.x + threadIdx.x;
    if (idx >= (N_LAYERS-1)*GCN_D*64) return;
    int li = idx >> 13;
    int r  = idx & 8191;
    int n  = r >> 6, kp = r & 63;
    const float* wl = gcn_w + (size_t)li*GCN_D*GCN_D;
    __half2 h = __floats2half2_rn(wl[(2*kp)*GCN_D + n], wl[(2*kp+1)*GCN_D + n]);
    g_WPk[li*128*PST + n*PST + kp] = *(uint32_t*)&h;
}

// Pack mlp_w1 into fragment layout [n(256, zero-pad >=200)][kpair], fp16.
__global__ void prep_w1_kernel(const float* __restrict__ mlp_w1) {
    int idx = blockIdx.x * blockDim.x + threadIdx.x;
    if (idx >= 256*W1ST) return;
    int n = idx >> 6, kp = idx & 63;
    float w0 = 0.f, w1 = 0.f;
    if (n < MLP_H) {
        w0 = mlp_w1[(2*kp)*MLP_H + n];
        w1 = mlp_w1[(2*kp+1)*MLP_H + n];
    }
    __half2 h = __floats2half2_rn(w0, w1);
    g_W1k[idx] = *(uint32_t*)&h;
}

__global__ __launch_bounds__(NTHREADS, 2) void nb101_main(
    const float* __restrict__ adjs,
    const int*   __restrict__ op_inds,
    const float* __restrict__ gcn_b,
    const float* __restrict__ mlp_b1,
    const float* __restrict__ mlp_w2,
    const float* __restrict__ mlp_b2,
    float* __restrict__ out,
    int Btot)
{
    extern __shared__ uint32_t smw[];
    float* smf = (float*)smw;
    int*   RMKp = (int*)(smw + RMK);
    int*   RGIp = (int*)(smw + RGI);
    float* RRDp = (float*)(smw + RRD);

    const uint32_t smem_base = smem_u32(smw);
    const int t  = threadIdx.x;
    const int tx = t & 31;
    const int ty = t >> 5;           // warp id 0..7 (also: graph id for aux phases)
    const int gq = tx >> 2;          // mma group id (0..7)
    const int tq = tx & 3;           // thread-in-group
    const int mw = ty >> 2;          // warp m-tile group (rows mw*32, 0..1)
    const int nw = ty & 3;           // warp n-tile (cols nw*32)
    const int gbase = blockIdx.x * G;

    // kick off async copy of layer-1 W fragments into smem
    {
        const uint4* srcW = (const uint4*)(g_WPk);
        uint32_t dW = smem_base + WPS*4;
        for (int i = t; i < 128*PST/4; i += NTHREADS)
            cpa16(dW + i*16, srcW + i);
        asm volatile("cp.async.commit_group;" ::: "memory");
    }

    // stage gate rows (layers 1..4, padded GST) and biases (all layers)
    for (int i = t; i < 24*GCN_D; i += NTHREADS)
        smf[GSo + (i >> 7)*GST + (i & 127)] = g_gate[6*GCN_D + i];
    for (int i = t; i < N_LAYERS*GCN_D; i += NTHREADS) smf[BSo + i] = gcn_b[i];
    // zero pad rows (g*8+7) of XP once
    for (int i = t; i < 8*64; i += NTHREADS) {
        int r = (i >> 6)*8 + 7, w = i & 63;
        smw[XPH + r*PST + w] = 0u;
        smw[XPL + r*PST + w] = 0u;
    }

    // per-row metadata; rows = g*8+u, u=7 is pad
    if (t < NROWS) {
        int g = t >> 3, u = t & 7;
        int m = 0, gi = 0; float rw = 0.f;
        int batch = gbase + g;
        if (u < 7 && batch < Btot) {
            const float* arow = adjs + (size_t)batch*(V*V) + u*V;
            m = 1 << u;
            #pragma unroll
            for (int v2 = 0; v2 < V; v2++) if (arow[v2] != 0.f) m |= 1 << v2;
            if (u == 0)        { gi = 0; rw = 0.f; }
            else if (u == V-1) { gi = 5; rw = 1.f/6.f; }
            else {
                int op = op_inds[(size_t)batch*(V-2) + (u-1)];
                gi = 1 + op;
                rw = (op != NONE_OP) ? (1.f/6.f) : 0.f;
            }
        }
        RMKp[t] = m; RGIp[t] = gi; RRDp[t] = rw;
    }
    __syncthreads();

    // ----- fused layer 0 + first AY, fully in registers -----
    // warp ty owns graph ty; lane owns col-words tx and tx+32
    #pragma unroll
    for (int j = 0; j < 2; j++) {
        const int wix = tx + j*32, c0 = 2*wix;
        float2 sv[V];
        #pragma unroll
        for (int v = 0; v < V; v++) sv[v] = __ldg((const float2*)(g_s0 + v*GCN_D + c0));
        const float2 b2v = *(const float2*)(smf + BSo + c0);
        float2 y1[V];
        #pragma unroll
        for (int u = 0; u < V; u++) {
            int row = ty*8 + u;
            int m = RMKp[row];
            float s0 = 0.f, s1 = 0.f;
            #pragma unroll
            for (int v = 0; v < V; v++)
                if ((m >> v) & 1) { s0 += sv[v].x; s1 += sv[v].y; }
            const float2 g2 = __ldg((const float2*)(g_gate + RGIp[row]*GCN_D + c0));
            y1[u].x = fmaxf(g2.x*s0 + b2v.x, 0.f);
            y1[u].y = fmaxf(g2.y*s1 + b2v.y, 0.f);
        }
        #pragma unroll
        for (int u = 0; u < V; u++) {
            int row = ty*8 + u;
            int m = RMKp[row];
            float s0 = 0.f, s1 = 0.f;
            #pragma unroll
            for (int v = 0; v < V; v++)
                if ((m >> v) & 1) { s0 += y1[v].x; s1 += y1[v].y; }
            uint32_t h, l;
            split2(s0, s1, h, l);
            smw[XPH + row*PST + wix] = h;
            smw[XPL + row*PST + wix] = l;
        }
    }

    // ldmatrix lane addresses (bytes), computed once
    const int L = tx;
    const int aRowOff = (L & 7) + ((L >> 3) & 1)*8;
    const int aKw     = ((L >> 4) & 1)*4;
    const uint32_t aAddrH0 = smem_base + (uint32_t)(XPH + (mw*32 + aRowOff)*PST + aKw)*4;
    const uint32_t aAddrL0 = smem_base + (uint32_t)(XPL + (mw*32 + aRowOff)*PST + aKw)*4;
    const uint32_t aAddrH1 = aAddrH0 + 16*PST*4;
    const uint32_t aAddrL1 = aAddrL0 + 16*PST*4;
    const int bCol = nw*32 + ((L >> 4) & 1)*8 + (L & 7);
    const int bKw  = ((L >> 3) & 1)*4;
    const uint32_t b0W = smem_base + (uint32_t)(WPS + bCol*PST + bKw)*4;
    const uint32_t b1W = b0W + 16*PST*4;

    // ----- layers 1..4 on tensor cores (2-pass split-fp16 A, fp16 W) -----
    for (int li = 1; li < N_LAYERS; li++) {
        if (li > 1) {
            // AY: warp ty owns graph ty; read Y pairs, masked sums, write AP in place
            #pragma unroll
            for (int j = 0; j < 2; j++) {
                const int wix = tx + j*32;
                float2 yv[V];
                #pragma unroll
                for (int v = 0; v < V; v++) {
                    int row = ty*8 + v;
                    yv[v] = join2(smw[XPH + row*PST + wix], smw[XPL + row*PST + wix]);
                }
                #pragma unroll
                for (int u = 0; u < V; u++) {
                    int row = ty*8 + u;
                    int m = RMKp[row];
                    float s0 = 0.f, s1 = 0.f;
                    #pragma unroll
                    for (int v = 0; v < V; v++)
                        if ((m >> v) & 1) { s0 += yv[v].x; s1 += yv[v].y; }
                    uint32_t h, l;
                    split2(s0, s1, h, l);
                    smw[XPH + row*PST + wix] = h;
                    smw[XPL + row*PST + wix] = l;
                }
            }
        }
        asm volatile("cp.async.wait_group 0;" ::: "memory");
        __syncthreads();   // B1: W_li staged; AP visible CTA-wide

        // GEMM: D(32x32 per warp, 2 m16 halves) = AP @ W, 2-pass
        float d[2][4][4];
        #pragma unroll
        for (int mt = 0; mt < 2; mt++)
            #pragma unroll
            for (int nt = 0; nt < 4; nt++)
                #pragma unroll
                for (int j = 0; j < 4; j++) d[mt][nt][j] = 0.f;

        #pragma unroll
        for (int kt = 0; kt < 8; kt++) {
            const uint32_t off = kt*32;
            uint32_t ah0[4], al0[4], ah1[4], al1[4], bw[8];
            ldsm4(ah0, aAddrH0 + off);
            ldsm4(al0, aAddrL0 + off);
            ldsm4(ah1, aAddrH1 + off);
            ldsm4(al1, aAddrL1 + off);
            ldsm4(bw,     b0W + off);
            ldsm4(bw + 4, b1W + off);
            #pragma unroll
            for (int nt = 0; nt < 4; nt++) {
                mma16816(d[0][nt], ah0, bw + nt*2);
                mma16816(d[0][nt], al0, bw + nt*2);
                mma16816(d[1][nt], ah1, bw + nt*2);
                mma16816(d[1][nt], al1, bw + nt*2);
            }
        }
        __syncthreads();   // B2: all W_li + AP reads done

        // prefetch next layer's W (overlaps epilogue + next AY)
        if (li < N_LAYERS - 1) {
            const uint4* srcW = (const uint4*)(g_WPk + (size_t)li*128*PST);
            uint32_t dW = smem_base + WPS*4;
            for (int i = t; i < 128*PST/4; i += NTHREADS)
                cpa16(dW + i*16, srcW + i);
            asm volatile("cp.async.commit_group;" ::: "memory");
        }

        // epilogue: y = gate*d + b (+relu), write fp16 pairs into XP
        const bool last = (li == N_LAYERS - 1);
        #pragma unroll
        for (int mt = 0; mt < 2; mt++) {
            const int R = mw*32 + mt*16 + gq;
            #pragma unroll
            for (int nt = 0; nt < 4; nt++) {
                int C = nw*32 + nt*8 + 2*tq;
                float2 g0 = *(const float2*)(smf + GSo + ((li-1)*6 + RGIp[R])*GST + C);
                float2 g1 = *(const float2*)(smf + GSo + ((li-1)*6 + RGIp[R+8])*GST + C);
                float2 bb = *(const float2*)(smf + BSo + li*GCN_D + C);
                float y0 = g0.x*d[mt][nt][0] + bb.x;
                float y1 = g0.y*d[mt][nt][1] + bb.y;
                float y2 = g1.x*d[mt][nt][2] + bb.x;
                float y3 = g1.y*d[mt][nt][3] + bb.y;
                if (!last) {
                    y0 = fmaxf(y0, 0.f); y1 = fmaxf(y1, 0.f);
                    y2 = fmaxf(y2, 0.f); y3 = fmaxf(y3, 0.f);
                }
                uint32_t h, l;
                split2(y0, y1, h, l);
                smw[XPH + R*PST + (C >> 1)] = h;
                smw[XPL + R*PST + (C >> 1)] = l;
                split2(y2, y3, h, l);
                smw[XPH + (R+8)*PST + (C >> 1)] = h;
                smw[XPL + (R+8)*PST + (C >> 1)] = l;
            }
        }
        BAR_MW(mw);        // mw-local: this group's Y ready for its own AY/readout
    }

    // ----- readout: z[g=ty] = sum_u rw*Y[g*8+u] into regs -----
    float z0[2], z1[2];
    #pragma unroll
    for (int j = 0; j < 2; j++) {
        const int wix = tx + j*32;
        float a0 = 0.f, a1 = 0.f;
        #pragma unroll
        for (int u = 0; u < V; u++) {
            int row = ty*8 + u;
            float rw = RRDp[row];
            float2 yv = join2(smw[XPH + row*PST + wix], smw[XPL + row*PST + wix]);
            a0 += rw*yv.x; a1 += rw*yv.y;
        }
        z0[j] = a0; z1[j] = a1;
    }
    __syncthreads();       // all Y reads complete before z overwrites rows 0..15
    #pragma unroll
    for (int j = 0; j < 2; j++) {
        const int wix = tx + j*32;
        uint32_t h, l;
        split2(z0[j], z1[j], h, l);
        smw[XPH + ty*PST + wix] = h;
        smw[XPL + ty*PST + wix] = l;
    }
    // zero rows 8..15 (pad rows of the MLP m16 tile)
    for (int i = t; i < 8*64; i += NTHREADS) {
        int r = 8 + (i >> 6), w = i & 63;
        smw[XPH + r*PST + w] = 0u;
        smw[XPL + r*PST + w] = 0u;
    }
    __syncthreads();

    // ----- MLP layer 1 via MMA: h(16 x 256pad) = z @ w1; fold relu+w2 reduction -----
    // 8 warps x one 32-col n-tile each
    {
        const uint32_t zAddrH = smem_base + (uint32_t)(XPH + aRowOff*PST + aKw)*4;
        const uint32_t zAddrL = smem_base + (uint32_t)(XPL + aRowOff*PST + aKw)*4;
        float d[4][4];
        #pragma unroll
        for (int nt = 0; nt < 4; nt++)
            #pragma unroll
            for (int j = 0; j < 4; j++) d[nt][j] = 0.f;
        #pragma unroll
        for (int kt = 0; kt < 8; kt++) {
            const int kb = kt*8 + tq;
            uint32_t ah[4], al[4], bw[2];
            ldsm4(ah, zAddrH + kt*32);
            ldsm4(al, zAddrL + kt*32);
            #pragma unroll
            for (int nt = 0; nt < 4; nt++) {
                int rn = (ty*32 + nt*8 + gq)*W1ST + kb;
                bw[0] = __ldg(g_W1k + rn); bw[1] = __ldg(g_W1k + rn + 4);
                mma16816(d[nt], ah, bw);
                mma16816(d[nt], al, bw);
            }
        }

        // bias + relu + w2 scale; rows gq (graph gq); rows gq+8 are zero pad
        float p0 = 0.f;
        #pragma unroll
        for (int nt = 0; nt < 4; nt++) {
            #pragma unroll
            for (int e = 0; e < 2; e++) {
                int j = ty*32 + nt*8 + 2*tq + e;
                if (j < MLP_H) {
                    float b1v = __ldg(mlp_b1 + j);
                    float w2v = __ldg(mlp_w2 + j);
                    p0 += fmaxf(d[nt][e] + b1v, 0.f) * w2v;
                }
            }
        }
        p0 += __shfl_down_sync(0xffffffffu, p0, 1);
        p0 += __shfl_down_sync(0xffffffffu, p0, 2);
        if (tq == 0) smf[PARTo + gq*8 + ty] = p0;
    }
    __syncthreads();

    // final reduce: warp g (<8) reduces its 8 partials
    if (ty < G) {
        float p = (tx < 8) ? smf[PARTo + ty*8 + tx] : 0.f;
        #pragma unroll
        for (int o = 4; o > 0; o >>= 1) p += __shfl_down_sync(0xffffffffu, p, o);
        if (tx == 0 && (gbase + ty) < Btot) out[gbase + ty] = p + __ldg(mlp_b2);
    }
}

extern "C" void kernel_launch(void* const* d_in, const int* in_sizes, int n_in,
                              void* d_out, int out_size)
{
    const float* adjs           = (const float*)d_in[0];
    const int*   op_inds        = (const int*)  d_in[1];
    const float* input_node_emb = (const float*)d_in[2];
    const float* other_node_emb = (const float*)d_in[3];
    const float* input_op_emb   = (const float*)d_in[4];
    const float* op_emb_table   = (const float*)d_in[5];
    const float* output_op_emb  = (const float*)d_in[6];
    const float* xh_w           = (const float*)d_in[7];
    const float* xh_b           = (const float*)d_in[8];
    const float* gcn0_w         = (const float*)d_in[9];
    const float* gcn_w          = (const float*)d_in[10];
    const float* attn_w         = (const float*)d_in[11];
    const float* attn_b         = (const float*)d_in[12];
    const float* gcn_b          = (const float*)d_in[13];
    const float* mlp_w1         = (const float*)d_in[14];
    const float* mlp_b1         = (const float*)d_in[15];
    const float* mlp_w2         = (const float*)d_in[16];
    const float* mlp_b2         = (const float*)d_in[17];
    float* out = (float*)d_out;

    int Btot = in_sizes[0] / (V*V);

    precompute_kernel<<<1, 256>>>(input_node_emb, other_node_emb, input_op_emb,
                                  op_emb_table, output_op_emb, xh_w, xh_b,
                                  gcn0_w, attn_w, attn_b);
    prep_w_kernel<<<((N_LAYERS-1)*GCN_D*64 + 255)/256, 256>>>(gcn_w);
    prep_w1_kernel<<<(256*W1ST + 255)/256, 256>>>(mlp_w1);

    size_t smem = SMEM_WORDS * sizeof(uint32_t);
    cudaFuncSetAttribute(nb101_main, cudaFuncAttributeMaxDynamicSharedMemorySize, (int)smem);
    int grid = (Btot + G - 1) / G;
    nb101_main<<<grid, NTHREADS, smem>>>(adjs, op_inds, gcn_b,
                                         mlp_b1, mlp_w2, mlp_b2, out, Btot);
}